// round 10
// baseline (speedup 1.0000x reference)
#include <cuda_runtime.h>
#include <cuda_fp16.h>
#include <math.h>
#include <stdint.h>

#define BB    32
#define HRESD 56
#define WRESD 56
#define CCH   256
#define LLEN  (HRESD*WRESD)          // 3136
#define ROWS  (BB*LLEN)              // 100352
#define NHH   8
#define HD    32
#define GW    7
#define NWT   49
#define NWIN  64
#define BWIN  (BB*NWIN)              // 2048
#define HID   1024
#define QSCALE 0.17677669529663687f

// ---------------- scratch ---------------------------------------------------
__device__ __align__(128) __half g_xnh [(size_t)ROWS*CCH];   // LN out (fp16)
__device__ __align__(128) __half g_awinh[(size_t)ROWS*CCH];  // attn out (fp16)
__device__ __align__(128) __half g_hidh[(size_t)ROWS*HID];   // gelu out (fp16)
__device__ __align__(128) __half g_wth [786432];             // weights fp16, transposed
__device__ __align__(128) __half g_q   [(size_t)BWIN*NHH*NWT*HD];
__device__ __align__(128) __half g_k   [(size_t)BWIN*NHH*NWT*HD];
__device__ __align__(128) __half g_v   [(size_t)BWIN*NHH*NWT*HD];
__device__ float g_x1  [(size_t)ROWS*CCH];
__device__ float g_pos [169*NHH];

#define WOFF_QKV  0
#define WOFF_PROJ 196608
#define WOFF_FC1  262144
#define WOFF_FC2  524288

// ---------------- helpers ----------------------------------------------------
__device__ __forceinline__ uint32_t smem_u32(const void* p) {
    uint32_t a;
    asm("{ .reg .u64 t; cvta.to.shared.u64 t, %1; cvt.u32.u64 %0, t; }" : "=r"(a) : "l"(p));
    return a;
}
__device__ __forceinline__ void ldsm4(uint32_t* r, uint32_t addr) {
    asm volatile("ldmatrix.sync.aligned.m8n8.x4.shared.b16 {%0,%1,%2,%3}, [%4];"
                 : "=r"(r[0]), "=r"(r[1]), "=r"(r[2]), "=r"(r[3]) : "r"(addr));
}
__device__ __forceinline__ void mma16816(float* c, const uint32_t* a, const uint32_t* b) {
    asm volatile("mma.sync.aligned.m16n8k16.row.col.f32.f16.f16.f32 "
                 "{%0,%1,%2,%3}, {%4,%5,%6,%7}, {%8,%9}, {%0,%1,%2,%3};"
                 : "+f"(c[0]), "+f"(c[1]), "+f"(c[2]), "+f"(c[3])
                 : "r"(a[0]), "r"(a[1]), "r"(a[2]), "r"(a[3]), "r"(b[0]), "r"(b[1]));
}
#define CP16(dst, src) asm volatile("cp.async.cg.shared.global [%0], [%1], 16;" :: "r"(dst), "l"(src))
#define CP_COMMIT()    asm volatile("cp.async.commit_group;")
#define CP_WAIT0()     asm volatile("cp.async.wait_group 0;")
#define CP_WAIT1()     asm volatile("cp.async.wait_group 1;")

#define SSTR    72
#define ARR_B   (128*SSTR*2)           // 18432 B
#define STAGE_B (2*ARR_B)              // Ah + Bh = 36864 B
#define SMEM_TOT (3*STAGE_B)           // 110592 B -> 2 CTAs/SM

// ---------------- 3-stage fp16 GEMM: 128x128 tile, BK=64 --------------------
// EPI: 0=QKV  1=PROJ  2=FC1+GELU  3=FC2+res
template<int EPI, int NC, int KC>
__global__ __launch_bounds__(256, 2) void gemm_mma(size_t woff,
                                                   const float* __restrict__ bias,
                                                   const float* __restrict__ X,
                                                   float* __restrict__ Out) {
    extern __shared__ char smc[];
    uint32_t smb = smem_u32(smc);

    const __half* A_g  = (EPI == 1) ? g_awinh : (EPI == 3 ? g_hidh : g_xnh);
    const __half* Bh_g = g_wth + woff;

    int tid  = threadIdx.x;
    int lane = tid & 31, wid = tid >> 5;
    int warpM = wid & 3, warpN = wid >> 2;        // 4 x 2 warp grid, 32x64 each
    int rbase = blockIdx.y * 128;
    int cbase = blockIdx.x * 128;

    float acc[2][8][4];
    #pragma unroll
    for (int mi = 0; mi < 2; mi++)
        #pragma unroll
        for (int nj = 0; nj < 8; nj++)
            #pragma unroll
            for (int e = 0; e < 4; e++) acc[mi][nj][e] = 0.f;

    const int arow = tid >> 3;
    const int kc8  = (tid & 7) * 8;

    // hoisted ldsm base offsets (bytes)
    const uint32_t a_off = (uint32_t)((warpM*32 + (lane & 15))*SSTR + ((lane & 16) >> 1)) * 2;
    const uint32_t b_off = (uint32_t)((warpN*64 + (lane & 7) + ((lane & 16) >> 1))*SSTR + (lane & 8)) * 2;

    auto issueTile = [&](int t) {
        int kt = t * 64;
        uint32_t sb = smb + (uint32_t)((t % 3) * STAGE_B);
        #pragma unroll
        for (int u = 0; u < 4; u++) {
            int row = u*32 + arow;
            CP16(sb + (uint32_t)((row*SSTR + kc8)*2),
                 A_g + (size_t)(rbase + row)*KC + kt + kc8);
        }
        #pragma unroll
        for (int u = 0; u < 4; u++) {
            int row = u*32 + arow;
            CP16(sb + (uint32_t)(ARR_B + (row*SSTR + kc8)*2),
                 Bh_g + (size_t)(cbase + row)*KC + kt + kc8);
        }
    };

    const int T = KC / 64;
    issueTile(0); CP_COMMIT();
    issueTile(1); CP_COMMIT();

    for (int t = 0; t < T; t++) {
        if (t + 1 < T) { CP_WAIT1(); } else { CP_WAIT0(); }
        __syncthreads();
        if (t + 2 < T) { issueTile(t + 2); CP_COMMIT(); }

        uint32_t ahb = smb + (uint32_t)((t % 3) * STAGE_B);
        uint32_t bhb = ahb + ARR_B;

        #pragma unroll
        for (int k0 = 0; k0 < 64; k0 += 16) {
            uint32_t a_h[2][4];
            ldsm4(a_h[0], ahb + a_off + k0*2);
            ldsm4(a_h[1], ahb + a_off + 16*SSTR*2 + k0*2);
            #pragma unroll
            for (int j = 0; j < 4; j++) {
                uint32_t r[4];
                ldsm4(r, bhb + b_off + (uint32_t)(j*16*SSTR)*2 + k0*2);
                mma16816(acc[0][j*2],   a_h[0], r);
                mma16816(acc[0][j*2+1], a_h[0], r+2);
                mma16816(acc[1][j*2],   a_h[1], r);
                mma16816(acc[1][j*2+1], a_h[1], r+2);
            }
        }
    }

    // ---- epilogue: per-row precompute, paired wide stores -------------------
    #pragma unroll
    for (int mi = 0; mi < 2; mi++)
        #pragma unroll
        for (int eh = 0; eh < 2; eh++) {
            int row = rbase + warpM*32 + mi*16 + (lane >> 2) + eh*8;

            if (EPI == 0) {
                int b  = row / LLEN, l = row % LLEN;
                int hh = l / WRESD, wc = l % WRESD;
                int wh = hh / GW, ii = hh % GW;
                int wn = wc / GW, jj = wc % GW;
                int Bidx = b*NWIN + wh*8 + wn;
                int n = ii*GW + jj;
                size_t rb = (size_t)Bidx*(NHH*NWT*HD) + (size_t)n*HD;
                #pragma unroll
                for (int nj = 0; nj < 8; nj++) {
                    int c = cbase + warpN*64 + nj*8 + (lane & 3)*2;
                    float2 bv = *(const float2*)&bias[c];
                    float v0 = acc[mi][nj][eh*2+0] + bv.x;
                    float v1 = acc[mi][nj][eh*2+1] + bv.y;
                    int sect = c >> 8;
                    int head = (c >> 5) & 7;
                    int d    = c & 31;
                    size_t idx = rb + (size_t)head*(NWT*HD) + d;
                    if (sect == 0)
                        *(__half2*)&g_q[idx] = __floats2half2_rn(v0*QSCALE, v1*QSCALE);
                    else if (sect == 1)
                        *(__half2*)&g_k[idx] = __floats2half2_rn(v0, v1);
                    else
                        *(__half2*)&g_v[idx] = __floats2half2_rn(v0, v1);
                }
            } else if (EPI == 1) {
                int Bidx = row / NWT, n = row % NWT;
                int b  = Bidx / NWIN, wi = Bidx % NWIN;
                int wh = wi / 8, wn = wi % 8;
                int ii = n / GW, jj = n % GW;
                int l  = (wh*GW + ii)*WRESD + wn*GW + jj;
                size_t rowoff = ((size_t)b*LLEN + l)*CCH;
                #pragma unroll
                for (int nj = 0; nj < 8; nj++) {
                    int c = cbase + warpN*64 + nj*8 + (lane & 3)*2;
                    float2 bv = *(const float2*)&bias[c];
                    float2 xv = *(const float2*)&X[rowoff + c];
                    *(float2*)&g_x1[rowoff + c] =
                        make_float2(xv.x + acc[mi][nj][eh*2+0] + bv.x,
                                    xv.y + acc[mi][nj][eh*2+1] + bv.y);
                }
            } else if (EPI == 2) {
                size_t rowoff = (size_t)row*HID;
                #pragma unroll
                for (int nj = 0; nj < 8; nj++) {
                    int c = cbase + warpN*64 + nj*8 + (lane & 3)*2;
                    float2 bv = *(const float2*)&bias[c];
                    float v0 = acc[mi][nj][eh*2+0] + bv.x;
                    float v1 = acc[mi][nj][eh*2+1] + bv.y;
                    float g0 = 0.5f*v0*(1.f + erff(v0*0.70710678118654752f));
                    float g1 = 0.5f*v1*(1.f + erff(v1*0.70710678118654752f));
                    *(__half2*)&g_hidh[rowoff + c] = __floats2half2_rn(g0, g1);
                }
            } else {
                size_t rowoff = (size_t)row*CCH;
                #pragma unroll
                for (int nj = 0; nj < 8; nj++) {
                    int c = cbase + warpN*64 + nj*8 + (lane & 3)*2;
                    float2 bv = *(const float2*)&bias[c];
                    float2 xv = *(const float2*)&g_x1[rowoff + c];
                    *(float2*)&Out[rowoff + c] =
                        make_float2(xv.x + acc[mi][nj][eh*2+0] + bv.x,
                                    xv.y + acc[mi][nj][eh*2+1] + bv.y);
                }
            }
        }
}

// ---------------- DynamicPosBias MLP (device fn, called from prep) -----------
__device__ __forceinline__ void pos_stage(float* t, const float* g, const float* b,
                                          const float* w, const float* wb, int outn) {
    float mu = 0.f;
    #pragma unroll
    for (int p = 0; p < 16; p++) mu += t[p];
    mu *= (1.f/16.f);
    float var = 0.f;
    #pragma unroll
    for (int p = 0; p < 16; p++) { float d = t[p]-mu; var += d*d; }
    var *= (1.f/16.f);
    float inv = rsqrtf(var + 1e-5f);
    float u[16];
    #pragma unroll
    for (int p = 0; p < 16; p++) {
        float z = (t[p]-mu)*inv*g[p] + b[p];
        u[p] = fmaxf(z, 0.f);
    }
    for (int q = 0; q < outn; q++) {
        float s = wb[q];
        #pragma unroll
        for (int p = 0; p < 16; p++) s += u[p]*w[p*outn + q];
        t[q] = s;
    }
}

// ---------------- fused prep: 4 weight transposes + pos MLP ------------------
// grid = 3073 blocks of 256; block 3072 runs the pos MLP.
__global__ void prep_kernel(const float* __restrict__ w_qkv,
                            const float* __restrict__ w_proj,
                            const float* __restrict__ w_fc1,
                            const float* __restrict__ w_fc2,
                            const float* pw, const float* pb,
                            const float* g1, const float* b1, const float* w1, const float* wb1,
                            const float* g2, const float* b2, const float* w2, const float* wb2,
                            const float* g3, const float* b3, const float* w3, const float* wb3) {
    if (blockIdx.x == 3072) {
        int i = threadIdx.x;
        if (i >= 169) return;
        float bh = (float)(i/13 - 6);
        float bw = (float)(i%13 - 6);
        float t[16];
        #pragma unroll
        for (int p = 0; p < 16; p++) t[p] = bh*pw[p] + bw*pw[16+p] + pb[p];
        pos_stage(t, g1, b1, w1, wb1, 16);
        pos_stage(t, g2, b2, w2, wb2, 16);
        pos_stage(t, g3, b3, w3, wb3, NHH);
        #pragma unroll
        for (int h = 0; h < NHH; h++) g_pos[i*NHH + h] = t[h];
        return;
    }
    int idx = blockIdx.x*256 + threadIdx.x;   // == destination offset in g_wth
    const float* w; int K, N, off;
    if (idx < WOFF_PROJ)      { w = w_qkv;  K = 256;  N = 768;  off = WOFF_QKV;  }
    else if (idx < WOFF_FC1)  { w = w_proj; K = 256;  N = 256;  off = WOFF_PROJ; }
    else if (idx < WOFF_FC2)  { w = w_fc1;  K = 256;  N = 1024; off = WOFF_FC1;  }
    else                      { w = w_fc2;  K = 1024; N = 256;  off = WOFF_FC2;  }
    int local = idx - off;
    int n = local / K, k = local - n*K;
    g_wth[idx] = __float2half_rn(w[(size_t)k*N + n]);
}

// ---------------- LayerNorm: warp per row, 8 rows/block ----------------------
__global__ void ln_kernel(const float* __restrict__ xin,
                          const float* __restrict__ gamma,
                          const float* __restrict__ beta, int src) {
    int warp = threadIdx.x >> 5, lane = threadIdx.x & 31;
    int r = blockIdx.x*8 + warp;
    const float* in = src ? g_x1 : xin;
    const float4* p = (const float4*)&in[(size_t)r*CCH];
    float4 v0 = p[lane];
    float4 v1 = p[lane + 32];

    float s = v0.x+v0.y+v0.z+v0.w + v1.x+v1.y+v1.z+v1.w;
    #pragma unroll
    for (int o = 16; o; o >>= 1) s += __shfl_xor_sync(0xffffffffu, s, o);
    float mu = s * (1.f/256.f);

    float d0x=v0.x-mu, d0y=v0.y-mu, d0z=v0.z-mu, d0w=v0.w-mu;
    float d1x=v1.x-mu, d1y=v1.y-mu, d1z=v1.z-mu, d1w=v1.w-mu;
    float q = d0x*d0x+d0y*d0y+d0z*d0z+d0w*d0w + d1x*d1x+d1y*d1y+d1z*d1z+d1w*d1w;
    #pragma unroll
    for (int o = 16; o; o >>= 1) q += __shfl_xor_sync(0xffffffffu, q, o);
    float inv = rsqrtf(q * (1.f/256.f) + 1e-5f);

    const float4* gp = (const float4*)gamma;
    const float4* bp = (const float4*)beta;
    float4 g0 = gp[lane], g1v = gp[lane+32];
    float4 b0 = bp[lane], b1v = bp[lane+32];

    __half2 h0 = __floats2half2_rn(d0x*inv*g0.x + b0.x, d0y*inv*g0.y + b0.y);
    __half2 h1 = __floats2half2_rn(d0z*inv*g0.z + b0.z, d0w*inv*g0.w + b0.w);
    __half2 h2 = __floats2half2_rn(d1x*inv*g1v.x + b1v.x, d1y*inv*g1v.y + b1v.y);
    __half2 h3 = __floats2half2_rn(d1z*inv*g1v.z + b1v.z, d1w*inv*g1v.w + b1v.w);

    __half* outp = &g_xnh[(size_t)r*CCH];
    ((uint2*)outp)[lane]      = make_uint2(*(uint32_t*)&h0, *(uint32_t*)&h1);
    ((uint2*)outp)[lane + 32] = make_uint2(*(uint32_t*)&h2, *(uint32_t*)&h3);
}

// ---------------- Windowed attention: conflict-free + register-tiled ---------
#define QR 52                      // 49 rounded up to 4
__global__ void attn_kernel() {
    __shared__ float qs[QR][33];   // stride 33 floats: conflict-free row access
    __shared__ float ks[QR][33];
    __shared__ float vs[NWT][33];
    __shared__ float at[QR][50];

    int blk  = blockIdx.x;
    int head = blk & 7;
    int Bidx = blk >> 3;
    size_t base = (size_t)blk * NWT * HD;
    int tid = threadIdx.x;
    int lane = tid & 31, wid = tid >> 5;

    const __half2* qp = (const __half2*)&g_q[base];
    const __half2* kp = (const __half2*)&g_k[base];
    const __half2* vp = (const __half2*)&g_v[base];
    for (int i = tid; i < NWT*16; i += 256) {
        int r = i >> 4, d2 = (i & 15) * 2;
        float2 f;
        f = __half22float2(qp[i]); qs[r][d2] = f.x; qs[r][d2+1] = f.y;
        f = __half22float2(kp[i]); ks[r][d2] = f.x; ks[r][d2+1] = f.y;
        f = __half22float2(vp[i]); vs[r][d2] = f.x; vs[r][d2+1] = f.y;
    }
    if (tid < 96) {
        int r = 49 + tid/32, d = tid & 31;
        qs[r][d] = 0.f; ks[r][d] = 0.f;
    }
    __syncthreads();

    // ---- QK^T: 13x13 tiles of 4x4 -------------------------------------------
    if (tid < 169) {
        int rg = tid / 13, mg = tid % 13;
        int r0 = rg*4, m0 = mg*4;
        float acc[4][4];
        #pragma unroll
        for (int i = 0; i < 4; i++)
            #pragma unroll
            for (int j = 0; j < 4; j++) acc[i][j] = 0.f;
        #pragma unroll 4
        for (int d = 0; d < HD; d++) {
            float qv[4], kv[4];
            #pragma unroll
            for (int i = 0; i < 4; i++) qv[i] = qs[r0+i][d];
            #pragma unroll
            for (int j = 0; j < 4; j++) kv[j] = ks[m0+j][d];
            #pragma unroll
            for (int i = 0; i < 4; i++)
                #pragma unroll
                for (int j = 0; j < 4; j++) acc[i][j] += qv[i]*kv[j];
        }
        #pragma unroll
        for (int i = 0; i < 4; i++) {
            int r = r0 + i;
            if (r < NWT) {
                int rq = r/GW, rr = r%GW;
                #pragma unroll
                for (int j = 0; j < 4; j++) {
                    int m = m0 + j;
                    if (m < NWT) {
                        int dh = rq - m/GW + 6;
                        int dw = rr - m%GW + 6;
                        at[r][m] = acc[i][j] + g_pos[(dh*13 + dw)*NHH + head];
                    }
                }
            }
        }
    }
    __syncthreads();

    // ---- softmax: warp-parallel over rows -----------------------------------
    for (int r = wid; r < NWT; r += 8) {
        float v0 = at[r][lane];
        float v1 = (lane < NWT - 32) ? at[r][lane + 32] : -1e30f;
        float mx = fmaxf(v0, v1);
        #pragma unroll
        for (int o = 16; o; o >>= 1) mx = fmaxf(mx, __shfl_xor_sync(0xffffffffu, mx, o));
        float e0 = __expf(v0 - mx);
        float e1 = (lane < NWT - 32) ? __expf(v1 - mx) : 0.f;
        float s = e0 + e1;
        #pragma unroll
        for (int o = 16; o; o >>= 1) s += __shfl_xor_sync(0xffffffffu, s, o);
        float inv = 1.f / s;
        at[r][lane] = e0 * inv;
        if (lane < NWT - 32) at[r][lane + 32] = e1 * inv;
    }
    if (tid < 3*NWT) {
        int r = 49 + tid/NWT, m = tid % NWT;
        at[r][m] = 0.f;
    }
    __syncthreads();

    // ---- P*V: 25x8 tiles of 2 rows x 4 cols (200 active threads) ------------
    if (tid < 200) {
        int rg = tid >> 3, dg = tid & 7;
        int r0 = rg*2, d0 = dg*4;
        float acc[2][4];
        #pragma unroll
        for (int i = 0; i < 2; i++)
            #pragma unroll
            for (int j = 0; j < 4; j++) acc[i][j] = 0.f;
        #pragma unroll 7
        for (int m = 0; m < NWT; m++) {
            float av[2], vv[4];
            #pragma unroll
            for (int i = 0; i < 2; i++) av[i] = at[r0+i][m];
            #pragma unroll
            for (int j = 0; j < 4; j++) vv[j] = vs[m][d0+j];
            #pragma unroll
            for (int i = 0; i < 2; i++)
                #pragma unroll
                for (int j = 0; j < 4; j++) acc[i][j] += av[i]*vv[j];
        }
        #pragma unroll
        for (int i = 0; i < 2; i++) {
            int r = r0 + i;
            if (r < NWT) {
                size_t o = ((size_t)Bidx*NWT + r)*CCH + head*HD + d0;
                *(__half2*)&g_awinh[o]     = __floats2half2_rn(acc[i][0], acc[i][1]);
                *(__half2*)&g_awinh[o + 2] = __floats2half2_rn(acc[i][2], acc[i][3]);
            }
        }
    }
}

// ---------------- launch ----------------------------------------------------
extern "C" void kernel_launch(void* const* d_in, const int* in_sizes, int n_in,
                              void* d_out, int out_size) {
    const float* x        = (const float*)d_in[0];
    const float* norm1_g  = (const float*)d_in[1];
    const float* norm1_b  = (const float*)d_in[2];
    const float* qkv_w    = (const float*)d_in[3];
    const float* qkv_b    = (const float*)d_in[4];
    const float* proj_w   = (const float*)d_in[5];
    const float* proj_b   = (const float*)d_in[6];
    const float* pos_pw   = (const float*)d_in[7];
    const float* pos_pb   = (const float*)d_in[8];
    const float* p1g      = (const float*)d_in[9];
    const float* p1b      = (const float*)d_in[10];
    const float* p1w      = (const float*)d_in[11];
    const float* p1wb     = (const float*)d_in[12];
    const float* p2g      = (const float*)d_in[13];
    const float* p2b      = (const float*)d_in[14];
    const float* p2w      = (const float*)d_in[15];
    const float* p2wb     = (const float*)d_in[16];
    const float* p3g      = (const float*)d_in[17];
    const float* p3b      = (const float*)d_in[18];
    const float* p3w      = (const float*)d_in[19];
    const float* p3wb     = (const float*)d_in[20];
    const float* norm2_g  = (const float*)d_in[21];
    const float* norm2_b  = (const float*)d_in[22];
    const float* fc1_w    = (const float*)d_in[23];
    const float* fc1_b    = (const float*)d_in[24];
    const float* fc2_w    = (const float*)d_in[25];
    const float* fc2_b    = (const float*)d_in[26];
    float* out = (float*)d_out;

    cudaFuncSetAttribute(gemm_mma<0,768,256>,  cudaFuncAttributeMaxDynamicSharedMemorySize, SMEM_TOT);
    cudaFuncSetAttribute(gemm_mma<1,256,256>,  cudaFuncAttributeMaxDynamicSharedMemorySize, SMEM_TOT);
    cudaFuncSetAttribute(gemm_mma<2,1024,256>, cudaFuncAttributeMaxDynamicSharedMemorySize, SMEM_TOT);
    cudaFuncSetAttribute(gemm_mma<3,256,1024>, cudaFuncAttributeMaxDynamicSharedMemorySize, SMEM_TOT);

    // launch order: prep(0), ln1(1), qkv(2), attn(3) -> ncu profiles attn
    prep_kernel<<<3073, 256>>>(qkv_w, proj_w, fc1_w, fc2_w,
                               pos_pw, pos_pb, p1g, p1b, p1w, p1wb,
                               p2g, p2b, p2w, p2wb, p3g, p3b, p3w, p3wb);
    ln_kernel<<<ROWS/8, 256>>>(x, norm1_g, norm1_b, 0);
    gemm_mma<0,768,256><<<dim3(6, ROWS/128), 256, SMEM_TOT>>>(WOFF_QKV, qkv_b, nullptr, nullptr);
    attn_kernel<<<BWIN*NHH, 256>>>();
    gemm_mma<1,256,256><<<dim3(2, ROWS/128), 256, SMEM_TOT>>>(WOFF_PROJ, proj_b, x, nullptr);
    ln_kernel<<<ROWS/8, 256>>>(nullptr, norm2_g, norm2_b, 1);
    gemm_mma<2,1024,256><<<dim3(8, ROWS/128), 256, SMEM_TOT>>>(WOFF_FC1, fc1_b, nullptr, nullptr);
    gemm_mma<3,256,1024><<<dim3(2, ROWS/128), 256, SMEM_TOT>>>(WOFF_FC2, fc2_b, nullptr, out);
}

// round 11
// speedup vs baseline: 1.4468x; 1.4468x over previous
#include <cuda_runtime.h>
#include <cuda_fp16.h>
#include <math.h>
#include <stdint.h>

#define BB    32
#define HRESD 56
#define WRESD 56
#define CCH   256
#define LLEN  (HRESD*WRESD)          // 3136
#define ROWS  (BB*LLEN)              // 100352
#define NHH   8
#define HD    32
#define GW    7
#define NWT   49
#define NWIN  64
#define BWIN  (BB*NWIN)              // 2048
#define HID   1024
#define QSCALE 0.17677669529663687f

// ---------------- scratch ---------------------------------------------------
__device__ __align__(128) __half g_xnh [(size_t)ROWS*CCH];   // LN out (fp16)
__device__ __align__(128) __half g_awinh[(size_t)ROWS*CCH];  // attn out (fp16)
__device__ __align__(128) __half g_hidh[(size_t)ROWS*HID];   // gelu out (fp16)
__device__ __align__(128) __half g_wth [786432];             // weights fp16, transposed
__device__ __align__(128) __half g_q   [(size_t)BWIN*NHH*NWT*HD];
__device__ __align__(128) __half g_k   [(size_t)BWIN*NHH*NWT*HD];
__device__ __align__(128) __half g_v   [(size_t)BWIN*NHH*NWT*HD];
__device__ float g_x1  [(size_t)ROWS*CCH];
__device__ float g_pos [169*NHH];

#define WOFF_QKV  0
#define WOFF_PROJ 196608
#define WOFF_FC1  262144
#define WOFF_FC2  524288

// ---------------- helpers ----------------------------------------------------
__device__ __forceinline__ uint32_t smem_u32(const void* p) {
    uint32_t a;
    asm("{ .reg .u64 t; cvta.to.shared.u64 t, %1; cvt.u32.u64 %0, t; }" : "=r"(a) : "l"(p));
    return a;
}
__device__ __forceinline__ void ldsm4(uint32_t* r, uint32_t addr) {
    asm volatile("ldmatrix.sync.aligned.m8n8.x4.shared.b16 {%0,%1,%2,%3}, [%4];"
                 : "=r"(r[0]), "=r"(r[1]), "=r"(r[2]), "=r"(r[3]) : "r"(addr));
}
__device__ __forceinline__ void mma16816(float* c, const uint32_t* a, const uint32_t* b) {
    asm volatile("mma.sync.aligned.m16n8k16.row.col.f32.f16.f16.f32 "
                 "{%0,%1,%2,%3}, {%4,%5,%6,%7}, {%8,%9}, {%0,%1,%2,%3};"
                 : "+f"(c[0]), "+f"(c[1]), "+f"(c[2]), "+f"(c[3])
                 : "r"(a[0]), "r"(a[1]), "r"(a[2]), "r"(a[3]), "r"(b[0]), "r"(b[1]));
}
#define CP16(dst, src) asm volatile("cp.async.cg.shared.global [%0], [%1], 16;" :: "r"(dst), "l"(src))
#define CP_COMMIT()    asm volatile("cp.async.commit_group;")
#define CP_WAIT0()     asm volatile("cp.async.wait_group 0;")
#define CP_WAIT1()     asm volatile("cp.async.wait_group 1;")

#define SSTR    72
#define ARR_B   (128*SSTR*2)           // 18432 B
#define STAGE_B (2*ARR_B)              // Ah + Bh = 36864 B
#define SMEM_TOT (3*STAGE_B)           // 110592 B -> 2 CTAs/SM

// ---------------- 3-stage fp16 GEMM: 128x128 tile, BK=64 (R9-proven) ---------
// EPI: 0=QKV  1=PROJ  2=FC1+GELU  3=FC2+res
template<int EPI, int NC, int KC>
__global__ __launch_bounds__(256, 2) void gemm_mma(size_t woff,
                                                   const float* __restrict__ bias,
                                                   const float* __restrict__ X,
                                                   float* __restrict__ Out) {
    extern __shared__ char smc[];
    uint32_t smb = smem_u32(smc);

    const __half* A_g  = (EPI == 1) ? g_awinh : (EPI == 3 ? g_hidh : g_xnh);
    const __half* Bh_g = g_wth + woff;

    int tid  = threadIdx.x;
    int lane = tid & 31, wid = tid >> 5;
    int warpM = wid & 3, warpN = wid >> 2;        // 4 x 2 warp grid, 32x64 each
    int rbase = blockIdx.y * 128;
    int cbase = blockIdx.x * 128;

    float acc[2][8][4];
    #pragma unroll
    for (int mi = 0; mi < 2; mi++)
        #pragma unroll
        for (int nj = 0; nj < 8; nj++)
            #pragma unroll
            for (int e = 0; e < 4; e++) acc[mi][nj][e] = 0.f;

    const int arow = tid >> 3;
    const int kc8  = (tid & 7) * 8;

    auto issueTile = [&](int t) {
        int kt = t * 64;
        uint32_t sb = smb + (uint32_t)((t % 3) * STAGE_B);
        #pragma unroll
        for (int u = 0; u < 4; u++) {
            int row = u*32 + arow;
            CP16(sb + (uint32_t)((row*SSTR + kc8)*2),
                 A_g + (size_t)(rbase + row)*KC + kt + kc8);
        }
        #pragma unroll
        for (int u = 0; u < 4; u++) {
            int row = u*32 + arow;
            CP16(sb + (uint32_t)(ARR_B + (row*SSTR + kc8)*2),
                 Bh_g + (size_t)(cbase + row)*KC + kt + kc8);
        }
    };

    const int T = KC / 64;
    issueTile(0); CP_COMMIT();
    issueTile(1); CP_COMMIT();

    for (int t = 0; t < T; t++) {
        if (t + 1 < T) { CP_WAIT1(); } else { CP_WAIT0(); }
        __syncthreads();
        if (t + 2 < T) { issueTile(t + 2); CP_COMMIT(); }

        uint32_t ahb = smb + (uint32_t)((t % 3) * STAGE_B);
        uint32_t bhb = ahb + ARR_B;

        #pragma unroll
        for (int k0 = 0; k0 < 64; k0 += 16) {
            uint32_t a_h[2][4];
            #pragma unroll
            for (int mi = 0; mi < 2; mi++) {
                int row = warpM*32 + mi*16 + (lane & 15);
                int col = k0 + ((lane & 16) >> 1);
                ldsm4(a_h[mi], ahb + (uint32_t)(row*SSTR + col)*2);
            }
            #pragma unroll
            for (int j = 0; j < 4; j++) {
                int row = warpN*64 + j*16 + (lane & 7) + ((lane & 16) >> 1);
                int col = k0 + (lane & 8);
                uint32_t r[4];
                ldsm4(r, bhb + (uint32_t)(row*SSTR + col)*2);
                mma16816(acc[0][j*2],   a_h[0], r);
                mma16816(acc[0][j*2+1], a_h[0], r+2);
                mma16816(acc[1][j*2],   a_h[1], r);
                mma16816(acc[1][j*2+1], a_h[1], r+2);
            }
        }
    }

    // ---- epilogue: per-row precompute, paired wide stores -------------------
    #pragma unroll
    for (int mi = 0; mi < 2; mi++)
        #pragma unroll
        for (int eh = 0; eh < 2; eh++) {
            int row = rbase + warpM*32 + mi*16 + (lane >> 2) + eh*8;

            if (EPI == 0) {
                int b  = row / LLEN, l = row % LLEN;
                int hh = l / WRESD, wc = l % WRESD;
                int wh = hh / GW, ii = hh % GW;
                int wn = wc / GW, jj = wc % GW;
                int Bidx = b*NWIN + wh*8 + wn;
                int n = ii*GW + jj;
                size_t rb = (size_t)Bidx*(NHH*NWT*HD) + (size_t)n*HD;
                #pragma unroll
                for (int nj = 0; nj < 8; nj++) {
                    int c = cbase + warpN*64 + nj*8 + (lane & 3)*2;
                    float2 bv = *(const float2*)&bias[c];
                    float v0 = acc[mi][nj][eh*2+0] + bv.x;
                    float v1 = acc[mi][nj][eh*2+1] + bv.y;
                    int sect = c >> 8;
                    int head = (c >> 5) & 7;
                    int d    = c & 31;
                    size_t idx = rb + (size_t)head*(NWT*HD) + d;
                    if (sect == 0)
                        *(__half2*)&g_q[idx] = __floats2half2_rn(v0*QSCALE, v1*QSCALE);
                    else if (sect == 1)
                        *(__half2*)&g_k[idx] = __floats2half2_rn(v0, v1);
                    else
                        *(__half2*)&g_v[idx] = __floats2half2_rn(v0, v1);
                }
            } else if (EPI == 1) {
                int Bidx = row / NWT, n = row % NWT;
                int b  = Bidx / NWIN, wi = Bidx % NWIN;
                int wh = wi / 8, wn = wi % 8;
                int ii = n / GW, jj = n % GW;
                int l  = (wh*GW + ii)*WRESD + wn*GW + jj;
                size_t rowoff = ((size_t)b*LLEN + l)*CCH;
                #pragma unroll
                for (int nj = 0; nj < 8; nj++) {
                    int c = cbase + warpN*64 + nj*8 + (lane & 3)*2;
                    float2 bv = *(const float2*)&bias[c];
                    float2 xv = *(const float2*)&X[rowoff + c];
                    *(float2*)&g_x1[rowoff + c] =
                        make_float2(xv.x + acc[mi][nj][eh*2+0] + bv.x,
                                    xv.y + acc[mi][nj][eh*2+1] + bv.y);
                }
            } else if (EPI == 2) {
                size_t rowoff = (size_t)row*HID;
                #pragma unroll
                for (int nj = 0; nj < 8; nj++) {
                    int c = cbase + warpN*64 + nj*8 + (lane & 3)*2;
                    float2 bv = *(const float2*)&bias[c];
                    float v0 = acc[mi][nj][eh*2+0] + bv.x;
                    float v1 = acc[mi][nj][eh*2+1] + bv.y;
                    float g0 = 0.5f*v0*(1.f + erff(v0*0.70710678118654752f));
                    float g1 = 0.5f*v1*(1.f + erff(v1*0.70710678118654752f));
                    *(__half2*)&g_hidh[rowoff + c] = __floats2half2_rn(g0, g1);
                }
            } else {
                size_t rowoff = (size_t)row*CCH;
                #pragma unroll
                for (int nj = 0; nj < 8; nj++) {
                    int c = cbase + warpN*64 + nj*8 + (lane & 3)*2;
                    float2 bv = *(const float2*)&bias[c];
                    float2 xv = *(const float2*)&g_x1[rowoff + c];
                    *(float2*)&Out[rowoff + c] =
                        make_float2(xv.x + acc[mi][nj][eh*2+0] + bv.x,
                                    xv.y + acc[mi][nj][eh*2+1] + bv.y);
                }
            }
        }
}

// ---------------- weight transpose (fp16) -----------------------------------
__global__ void wsplit_kernel(const float* __restrict__ w, int K, int N, size_t off) {
    int idx = blockIdx.x*blockDim.x + threadIdx.x;
    if (idx >= K*N) return;
    int n = idx / K, k = idx - n*K;
    g_wth[off + idx] = __float2half_rn(w[(size_t)k*N + n]);
}

// ---------------- DynamicPosBias MLP ----------------------------------------
__device__ __forceinline__ void pos_stage(float* t, const float* g, const float* b,
                                          const float* w, const float* wb, int outn) {
    float mu = 0.f;
    #pragma unroll
    for (int p = 0; p < 16; p++) mu += t[p];
    mu *= (1.f/16.f);
    float var = 0.f;
    #pragma unroll
    for (int p = 0; p < 16; p++) { float d = t[p]-mu; var += d*d; }
    var *= (1.f/16.f);
    float inv = rsqrtf(var + 1e-5f);
    float u[16];
    #pragma unroll
    for (int p = 0; p < 16; p++) {
        float z = (t[p]-mu)*inv*g[p] + b[p];
        u[p] = fmaxf(z, 0.f);
    }
    for (int q = 0; q < outn; q++) {
        float s = wb[q];
        #pragma unroll
        for (int p = 0; p < 16; p++) s += u[p]*w[p*outn + q];
        t[q] = s;
    }
}

__global__ void pos_mlp_kernel(const float* pw, const float* pb,
                               const float* g1, const float* b1, const float* w1, const float* wb1,
                               const float* g2, const float* b2, const float* w2, const float* wb2,
                               const float* g3, const float* b3, const float* w3, const float* wb3) {
    int i = threadIdx.x;
    if (i >= 169) return;
    float bh = (float)(i/13 - 6);
    float bw = (float)(i%13 - 6);
    float t[16];
    #pragma unroll
    for (int p = 0; p < 16; p++) t[p] = bh*pw[p] + bw*pw[16+p] + pb[p];
    pos_stage(t, g1, b1, w1, wb1, 16);
    pos_stage(t, g2, b2, w2, wb2, 16);
    pos_stage(t, g3, b3, w3, wb3, NHH);
    #pragma unroll
    for (int h = 0; h < NHH; h++) g_pos[i*NHH + h] = t[h];
}

// ---------------- LayerNorm: warp per row, 8 rows/block ----------------------
__global__ void ln_kernel(const float* __restrict__ xin,
                          const float* __restrict__ gamma,
                          const float* __restrict__ beta, int src) {
    int warp = threadIdx.x >> 5, lane = threadIdx.x & 31;
    int r = blockIdx.x*8 + warp;
    const float* in = src ? g_x1 : xin;
    const float4* p = (const float4*)&in[(size_t)r*CCH];
    float4 v0 = p[lane];
    float4 v1 = p[lane + 32];

    float s = v0.x+v0.y+v0.z+v0.w + v1.x+v1.y+v1.z+v1.w;
    #pragma unroll
    for (int o = 16; o; o >>= 1) s += __shfl_xor_sync(0xffffffffu, s, o);
    float mu = s * (1.f/256.f);

    float d0x=v0.x-mu, d0y=v0.y-mu, d0z=v0.z-mu, d0w=v0.w-mu;
    float d1x=v1.x-mu, d1y=v1.y-mu, d1z=v1.z-mu, d1w=v1.w-mu;
    float q = d0x*d0x+d0y*d0y+d0z*d0z+d0w*d0w + d1x*d1x+d1y*d1y+d1z*d1z+d1w*d1w;
    #pragma unroll
    for (int o = 16; o; o >>= 1) q += __shfl_xor_sync(0xffffffffu, q, o);
    float inv = rsqrtf(q * (1.f/256.f) + 1e-5f);

    const float4* gp = (const float4*)gamma;
    const float4* bp = (const float4*)beta;
    float4 g0 = gp[lane], g1v = gp[lane+32];
    float4 b0 = bp[lane], b1v = bp[lane+32];

    __half2 h0 = __floats2half2_rn(d0x*inv*g0.x + b0.x, d0y*inv*g0.y + b0.y);
    __half2 h1 = __floats2half2_rn(d0z*inv*g0.z + b0.z, d0w*inv*g0.w + b0.w);
    __half2 h2 = __floats2half2_rn(d1x*inv*g1v.x + b1v.x, d1y*inv*g1v.y + b1v.y);
    __half2 h3 = __floats2half2_rn(d1z*inv*g1v.z + b1v.z, d1w*inv*g1v.w + b1v.w);

    __half* outp = &g_xnh[(size_t)r*CCH];
    ((uint2*)outp)[lane]      = make_uint2(*(uint32_t*)&h0, *(uint32_t*)&h1);
    ((uint2*)outp)[lane + 32] = make_uint2(*(uint32_t*)&h2, *(uint32_t*)&h3);
}

// ---------------- Windowed attention: 7x7 register tiles (min smem bytes) ----
__global__ void attn_kernel() {
    __shared__ float qs[NWT][33];   // stride 33: conflict-free
    __shared__ float ks[NWT][33];
    __shared__ float vs[NWT][33];
    __shared__ float at[NWT][50];

    int blk  = blockIdx.x;
    int head = blk & 7;
    int Bidx = blk >> 3;
    size_t base = (size_t)blk * NWT * HD;
    int tid = threadIdx.x;
    int lane = tid & 31, wid = tid >> 5;

    const __half2* qp = (const __half2*)&g_q[base];
    const __half2* kp = (const __half2*)&g_k[base];
    const __half2* vp = (const __half2*)&g_v[base];
    for (int i = tid; i < NWT*16; i += 256) {
        int r = i >> 4, d2 = (i & 15) * 2;
        float2 f;
        f = __half22float2(qp[i]); qs[r][d2] = f.x; qs[r][d2+1] = f.y;
        f = __half22float2(kp[i]); ks[r][d2] = f.x; ks[r][d2+1] = f.y;
        f = __half22float2(vp[i]); vs[r][d2] = f.x; vs[r][d2+1] = f.y;
    }
    __syncthreads();

    // ---- QK^T: 49 threads, 7x7 register tiles (49 = 7*7 exactly) ------------
    if (tid < 49) {
        int r0 = (tid / 7) * 7, m0 = (tid % 7) * 7;
        float acc[7][7];
        #pragma unroll
        for (int i = 0; i < 7; i++)
            #pragma unroll
            for (int j = 0; j < 7; j++) acc[i][j] = 0.f;
        #pragma unroll 4
        for (int d = 0; d < HD; d++) {
            float qv[7], kv[7];
            #pragma unroll
            for (int i = 0; i < 7; i++) qv[i] = qs[r0+i][d];
            #pragma unroll
            for (int j = 0; j < 7; j++) kv[j] = ks[m0+j][d];
            #pragma unroll
            for (int i = 0; i < 7; i++)
                #pragma unroll
                for (int j = 0; j < 7; j++) acc[i][j] += qv[i]*kv[j];
        }
        #pragma unroll
        for (int i = 0; i < 7; i++) {
            int r = r0 + i;
            int rq = r/GW, rr = r%GW;
            #pragma unroll
            for (int j = 0; j < 7; j++) {
                int m = m0 + j;
                int dh = rq - m/GW + 6;
                int dw = rr - m%GW + 6;
                at[r][m] = acc[i][j] + g_pos[(dh*13 + dw)*NHH + head];
            }
        }
    }
    __syncthreads();

    // ---- softmax: warp-parallel over rows -----------------------------------
    for (int r = wid; r < NWT; r += 8) {
        float v0 = at[r][lane];
        float v1 = (lane < NWT - 32) ? at[r][lane + 32] : -1e30f;
        float mx = fmaxf(v0, v1);
        #pragma unroll
        for (int o = 16; o; o >>= 1) mx = fmaxf(mx, __shfl_xor_sync(0xffffffffu, mx, o));
        float e0 = __expf(v0 - mx);
        float e1 = (lane < NWT - 32) ? __expf(v1 - mx) : 0.f;
        float s = e0 + e1;
        #pragma unroll
        for (int o = 16; o; o >>= 1) s += __shfl_xor_sync(0xffffffffu, s, o);
        float inv = 1.f / s;
        at[r][lane] = e0 * inv;
        if (lane < NWT - 32) at[r][lane + 32] = e1 * inv;
    }
    __syncthreads();

    // ---- P*V: 28 threads, 7 rows x 8 cols register tiles --------------------
    if (tid < 28) {
        int r0 = (tid >> 2) * 7, d0 = (tid & 3) * 8;
        float acc[7][8];
        #pragma unroll
        for (int i = 0; i < 7; i++)
            #pragma unroll
            for (int j = 0; j < 8; j++) acc[i][j] = 0.f;
        #pragma unroll 7
        for (int m = 0; m < NWT; m++) {
            float av[7], vv[8];
            #pragma unroll
            for (int i = 0; i < 7; i++) av[i] = at[r0+i][m];
            #pragma unroll
            for (int j = 0; j < 8; j++) vv[j] = vs[m][d0+j];
            #pragma unroll
            for (int i = 0; i < 7; i++)
                #pragma unroll
                for (int j = 0; j < 8; j++) acc[i][j] += av[i]*vv[j];
        }
        #pragma unroll
        for (int i = 0; i < 7; i++) {
            size_t o = ((size_t)Bidx*NWT + r0 + i)*CCH + head*HD + d0;
            #pragma unroll
            for (int j = 0; j < 8; j += 2)
                *(__half2*)&g_awinh[o + j] = __floats2half2_rn(acc[i][j], acc[i][j+1]);
        }
    }
}

// ---------------- launch ----------------------------------------------------
extern "C" void kernel_launch(void* const* d_in, const int* in_sizes, int n_in,
                              void* d_out, int out_size) {
    const float* x        = (const float*)d_in[0];
    const float* norm1_g  = (const float*)d_in[1];
    const float* norm1_b  = (const float*)d_in[2];
    const float* qkv_w    = (const float*)d_in[3];
    const float* qkv_b    = (const float*)d_in[4];
    const float* proj_w   = (const float*)d_in[5];
    const float* proj_b   = (const float*)d_in[6];
    const float* pos_pw   = (const float*)d_in[7];
    const float* pos_pb   = (const float*)d_in[8];
    const float* p1g      = (const float*)d_in[9];
    const float* p1b      = (const float*)d_in[10];
    const float* p1w      = (const float*)d_in[11];
    const float* p1wb     = (const float*)d_in[12];
    const float* p2g      = (const float*)d_in[13];
    const float* p2b      = (const float*)d_in[14];
    const float* p2w      = (const float*)d_in[15];
    const float* p2wb     = (const float*)d_in[16];
    const float* p3g      = (const float*)d_in[17];
    const float* p3b      = (const float*)d_in[18];
    const float* p3w      = (const float*)d_in[19];
    const float* p3wb     = (const float*)d_in[20];
    const float* norm2_g  = (const float*)d_in[21];
    const float* norm2_b  = (const float*)d_in[22];
    const float* fc1_w    = (const float*)d_in[23];
    const float* fc1_b    = (const float*)d_in[24];
    const float* fc2_w    = (const float*)d_in[25];
    const float* fc2_b    = (const float*)d_in[26];
    float* out = (float*)d_out;

    cudaFuncSetAttribute(gemm_mma<0,768,256>,  cudaFuncAttributeMaxDynamicSharedMemorySize, SMEM_TOT);
    cudaFuncSetAttribute(gemm_mma<1,256,256>,  cudaFuncAttributeMaxDynamicSharedMemorySize, SMEM_TOT);
    cudaFuncSetAttribute(gemm_mma<2,1024,256>, cudaFuncAttributeMaxDynamicSharedMemorySize, SMEM_TOT);
    cudaFuncSetAttribute(gemm_mma<3,256,1024>, cudaFuncAttributeMaxDynamicSharedMemorySize, SMEM_TOT);

    pos_mlp_kernel<<<1, 192>>>(pos_pw, pos_pb, p1g, p1b, p1w, p1wb,
                               p2g, p2b, p2w, p2wb, p3g, p3b, p3w, p3wb);
    ln_kernel<<<ROWS/8, 256>>>(x, norm1_g, norm1_b, 0);
    wsplit_kernel<<<(256*768+255)/256, 256>>>(qkv_w, 256, 768, WOFF_QKV);
    gemm_mma<0,768,256><<<dim3(6, ROWS/128), 256, SMEM_TOT>>>(WOFF_QKV, qkv_b, nullptr, nullptr);
    wsplit_kernel<<<(256*256+255)/256, 256>>>(proj_w, 256, 256, WOFF_PROJ);
    attn_kernel<<<BWIN*NHH, 256>>>();
    gemm_mma<1,256,256><<<dim3(2, ROWS/128), 256, SMEM_TOT>>>(WOFF_PROJ, proj_b, x, nullptr);
    wsplit_kernel<<<(256*1024+255)/256, 256>>>(fc1_w, 256, 1024, WOFF_FC1);
    ln_kernel<<<ROWS/8, 256>>>(nullptr, norm2_g, norm2_b, 1);
    gemm_mma<2,1024,256><<<dim3(8, ROWS/128), 256, SMEM_TOT>>>(WOFF_FC1, fc1_b, nullptr, nullptr);
    wsplit_kernel<<<(1024*256+255)/256, 256>>>(fc2_w, 1024, 256, WOFF_FC2);
    gemm_mma<3,256,1024><<<dim3(2, ROWS/128), 256, SMEM_TOT>>>(WOFF_FC2, fc2_b, nullptr, out);
}

// round 12
// speedup vs baseline: 1.4630x; 1.0112x over previous
#include <cuda_runtime.h>
#include <cuda_fp16.h>
#include <math.h>
#include <stdint.h>

#define BB    32
#define HRESD 56
#define WRESD 56
#define CCH   256
#define LLEN  (HRESD*WRESD)          // 3136
#define ROWS  (BB*LLEN)              // 100352
#define NHH   8
#define HD    32
#define GW    7
#define NWT   49
#define NWIN  64
#define BWIN  (BB*NWIN)              // 2048
#define HID   1024
#define QSCALE 0.17677669529663687f

// ---------------- scratch ---------------------------------------------------
__device__ __align__(128) __half g_xnh [(size_t)ROWS*CCH];   // LN out (fp16)
__device__ __align__(128) __half g_awinh[(size_t)ROWS*CCH];  // attn out (fp16)
__device__ __align__(128) __half g_hidh[(size_t)ROWS*HID];   // gelu out (fp16)
__device__ __align__(128) __half g_wth [786432];             // weights fp16, transposed
__device__ __align__(128) __half g_q   [(size_t)BWIN*NHH*NWT*HD];
__device__ __align__(128) __half g_k   [(size_t)BWIN*NHH*NWT*HD];
__device__ __align__(128) __half g_v   [(size_t)BWIN*NHH*NWT*HD];
__device__ float g_x1  [(size_t)ROWS*CCH];
__device__ float g_pos [169*NHH];

#define WOFF_QKV  0
#define WOFF_PROJ 196608
#define WOFF_FC1  262144
#define WOFF_FC2  524288

// ---------------- helpers ----------------------------------------------------
__device__ __forceinline__ uint32_t smem_u32(const void* p) {
    uint32_t a;
    asm("{ .reg .u64 t; cvta.to.shared.u64 t, %1; cvt.u32.u64 %0, t; }" : "=r"(a) : "l"(p));
    return a;
}
__device__ __forceinline__ void ldsm4(uint32_t* r, uint32_t addr) {
    asm volatile("ldmatrix.sync.aligned.m8n8.x4.shared.b16 {%0,%1,%2,%3}, [%4];"
                 : "=r"(r[0]), "=r"(r[1]), "=r"(r[2]), "=r"(r[3]) : "r"(addr));
}
__device__ __forceinline__ void mma16816(float* c, const uint32_t* a, const uint32_t* b) {
    asm volatile("mma.sync.aligned.m16n8k16.row.col.f32.f16.f16.f32 "
                 "{%0,%1,%2,%3}, {%4,%5,%6,%7}, {%8,%9}, {%0,%1,%2,%3};"
                 : "+f"(c[0]), "+f"(c[1]), "+f"(c[2]), "+f"(c[3])
                 : "r"(a[0]), "r"(a[1]), "r"(a[2]), "r"(a[3]), "r"(b[0]), "r"(b[1]));
}
#define CP16(dst, src) asm volatile("cp.async.cg.shared.global [%0], [%1], 16;" :: "r"(dst), "l"(src))
#define CP_COMMIT()    asm volatile("cp.async.commit_group;")
#define CP_WAIT0()     asm volatile("cp.async.wait_group 0;")
#define CP_WAIT1()     asm volatile("cp.async.wait_group 1;")

#define SSTR    72
#define ARR_B   (128*SSTR*2)           // 18432 B
#define STAGE_B (2*ARR_B)              // Ah + Bh = 36864 B
#define SMEM_TOT (3*STAGE_B)           // 110592 B -> 2 CTAs/SM

// ---------------- 3-stage fp16 GEMM: 128x128 tile, BK=64 (R9-proven) ---------
// EPI: 0=QKV  1=PROJ  2=FC1+GELU  3=FC2+res
template<int EPI, int NC, int KC>
__global__ __launch_bounds__(256, 2) void gemm_mma(size_t woff,
                                                   const float* __restrict__ bias,
                                                   const float* __restrict__ X,
                                                   float* __restrict__ Out) {
    extern __shared__ char smc[];
    uint32_t smb = smem_u32(smc);

    const __half* A_g  = (EPI == 1) ? g_awinh : (EPI == 3 ? g_hidh : g_xnh);
    const __half* Bh_g = g_wth + woff;

    int tid  = threadIdx.x;
    int lane = tid & 31, wid = tid >> 5;
    int warpM = wid & 3, warpN = wid >> 2;        // 4 x 2 warp grid, 32x64 each
    int rbase = blockIdx.y * 128;
    int cbase = blockIdx.x * 128;

    float acc[2][8][4];
    #pragma unroll
    for (int mi = 0; mi < 2; mi++)
        #pragma unroll
        for (int nj = 0; nj < 8; nj++)
            #pragma unroll
            for (int e = 0; e < 4; e++) acc[mi][nj][e] = 0.f;

    const int arow = tid >> 3;
    const int kc8  = (tid & 7) * 8;

    auto issueTile = [&](int t) {
        int kt = t * 64;
        uint32_t sb = smb + (uint32_t)((t % 3) * STAGE_B);
        #pragma unroll
        for (int u = 0; u < 4; u++) {
            int row = u*32 + arow;
            CP16(sb + (uint32_t)((row*SSTR + kc8)*2),
                 A_g + (size_t)(rbase + row)*KC + kt + kc8);
        }
        #pragma unroll
        for (int u = 0; u < 4; u++) {
            int row = u*32 + arow;
            CP16(sb + (uint32_t)(ARR_B + (row*SSTR + kc8)*2),
                 Bh_g + (size_t)(cbase + row)*KC + kt + kc8);
        }
    };

    const int T = KC / 64;
    issueTile(0); CP_COMMIT();
    issueTile(1); CP_COMMIT();

    for (int t = 0; t < T; t++) {
        if (t + 1 < T) { CP_WAIT1(); } else { CP_WAIT0(); }
        __syncthreads();
        if (t + 2 < T) { issueTile(t + 2); CP_COMMIT(); }

        uint32_t ahb = smb + (uint32_t)((t % 3) * STAGE_B);
        uint32_t bhb = ahb + ARR_B;

        #pragma unroll
        for (int k0 = 0; k0 < 64; k0 += 16) {
            uint32_t a_h[2][4];
            #pragma unroll
            for (int mi = 0; mi < 2; mi++) {
                int row = warpM*32 + mi*16 + (lane & 15);
                int col = k0 + ((lane & 16) >> 1);
                ldsm4(a_h[mi], ahb + (uint32_t)(row*SSTR + col)*2);
            }
            #pragma unroll
            for (int j = 0; j < 4; j++) {
                int row = warpN*64 + j*16 + (lane & 7) + ((lane & 16) >> 1);
                int col = k0 + (lane & 8);
                uint32_t r[4];
                ldsm4(r, bhb + (uint32_t)(row*SSTR + col)*2);
                mma16816(acc[0][j*2],   a_h[0], r);
                mma16816(acc[0][j*2+1], a_h[0], r+2);
                mma16816(acc[1][j*2],   a_h[1], r);
                mma16816(acc[1][j*2+1], a_h[1], r+2);
            }
        }
    }

    // ---- epilogue: per-row precompute, paired wide stores -------------------
    #pragma unroll
    for (int mi = 0; mi < 2; mi++)
        #pragma unroll
        for (int eh = 0; eh < 2; eh++) {
            int row = rbase + warpM*32 + mi*16 + (lane >> 2) + eh*8;

            if (EPI == 0) {
                int b  = row / LLEN, l = row % LLEN;
                int hh = l / WRESD, wc = l % WRESD;
                int wh = hh / GW, ii = hh % GW;
                int wn = wc / GW, jj = wc % GW;
                int Bidx = b*NWIN + wh*8 + wn;
                int n = ii*GW + jj;
                size_t rb = (size_t)Bidx*(NHH*NWT*HD) + (size_t)n*HD;
                #pragma unroll
                for (int nj = 0; nj < 8; nj++) {
                    int c = cbase + warpN*64 + nj*8 + (lane & 3)*2;
                    float2 bv = *(const float2*)&bias[c];
                    float v0 = acc[mi][nj][eh*2+0] + bv.x;
                    float v1 = acc[mi][nj][eh*2+1] + bv.y;
                    int sect = c >> 8;
                    int head = (c >> 5) & 7;
                    int d    = c & 31;
                    size_t idx = rb + (size_t)head*(NWT*HD) + d;
                    if (sect == 0)
                        *(__half2*)&g_q[idx] = __floats2half2_rn(v0*QSCALE, v1*QSCALE);
                    else if (sect == 1)
                        *(__half2*)&g_k[idx] = __floats2half2_rn(v0, v1);
                    else
                        *(__half2*)&g_v[idx] = __floats2half2_rn(v0, v1);
                }
            } else if (EPI == 1) {
                int Bidx = row / NWT, n = row % NWT;
                int b  = Bidx / NWIN, wi = Bidx % NWIN;
                int wh = wi / 8, wn = wi % 8;
                int ii = n / GW, jj = n % GW;
                int l  = (wh*GW + ii)*WRESD + wn*GW + jj;
                size_t rowoff = ((size_t)b*LLEN + l)*CCH;
                #pragma unroll
                for (int nj = 0; nj < 8; nj++) {
                    int c = cbase + warpN*64 + nj*8 + (lane & 3)*2;
                    float2 bv = *(const float2*)&bias[c];
                    float2 xv = *(const float2*)&X[rowoff + c];
                    *(float2*)&g_x1[rowoff + c] =
                        make_float2(xv.x + acc[mi][nj][eh*2+0] + bv.x,
                                    xv.y + acc[mi][nj][eh*2+1] + bv.y);
                }
            } else if (EPI == 2) {
                size_t rowoff = (size_t)row*HID;
                #pragma unroll
                for (int nj = 0; nj < 8; nj++) {
                    int c = cbase + warpN*64 + nj*8 + (lane & 3)*2;
                    float2 bv = *(const float2*)&bias[c];
                    float v0 = acc[mi][nj][eh*2+0] + bv.x;
                    float v1 = acc[mi][nj][eh*2+1] + bv.y;
                    float g0 = 0.5f*v0*(1.f + erff(v0*0.70710678118654752f));
                    float g1 = 0.5f*v1*(1.f + erff(v1*0.70710678118654752f));
                    *(__half2*)&g_hidh[rowoff + c] = __floats2half2_rn(g0, g1);
                }
            } else {
                size_t rowoff = (size_t)row*CCH;
                #pragma unroll
                for (int nj = 0; nj < 8; nj++) {
                    int c = cbase + warpN*64 + nj*8 + (lane & 3)*2;
                    float2 bv = *(const float2*)&bias[c];
                    float2 xv = *(const float2*)&g_x1[rowoff + c];
                    *(float2*)&Out[rowoff + c] =
                        make_float2(xv.x + acc[mi][nj][eh*2+0] + bv.x,
                                    xv.y + acc[mi][nj][eh*2+1] + bv.y);
                }
            }
        }
}

// ---------------- weight transpose (fp16) -----------------------------------
__global__ void wsplit_kernel(const float* __restrict__ w, int K, int N, size_t off) {
    int idx = blockIdx.x*blockDim.x + threadIdx.x;
    if (idx >= K*N) return;
    int n = idx / K, k = idx - n*K;
    g_wth[off + idx] = __float2half_rn(w[(size_t)k*N + n]);
}

// ---------------- DynamicPosBias MLP ----------------------------------------
__device__ __forceinline__ void pos_stage(float* t, const float* g, const float* b,
                                          const float* w, const float* wb, int outn) {
    float mu = 0.f;
    #pragma unroll
    for (int p = 0; p < 16; p++) mu += t[p];
    mu *= (1.f/16.f);
    float var = 0.f;
    #pragma unroll
    for (int p = 0; p < 16; p++) { float d = t[p]-mu; var += d*d; }
    var *= (1.f/16.f);
    float inv = rsqrtf(var + 1e-5f);
    float u[16];
    #pragma unroll
    for (int p = 0; p < 16; p++) {
        float z = (t[p]-mu)*inv*g[p] + b[p];
        u[p] = fmaxf(z, 0.f);
    }
    for (int q = 0; q < outn; q++) {
        float s = wb[q];
        #pragma unroll
        for (int p = 0; p < 16; p++) s += u[p]*w[p*outn + q];
        t[q] = s;
    }
}

__global__ void pos_mlp_kernel(const float* pw, const float* pb,
                               const float* g1, const float* b1, const float* w1, const float* wb1,
                               const float* g2, const float* b2, const float* w2, const float* wb2,
                               const float* g3, const float* b3, const float* w3, const float* wb3) {
    int i = threadIdx.x;
    if (i >= 169) return;
    float bh = (float)(i/13 - 6);
    float bw = (float)(i%13 - 6);
    float t[16];
    #pragma unroll
    for (int p = 0; p < 16; p++) t[p] = bh*pw[p] + bw*pw[16+p] + pb[p];
    pos_stage(t, g1, b1, w1, wb1, 16);
    pos_stage(t, g2, b2, w2, wb2, 16);
    pos_stage(t, g3, b3, w3, wb3, NHH);
    #pragma unroll
    for (int h = 0; h < NHH; h++) g_pos[i*NHH + h] = t[h];
}

// ---------------- LayerNorm: warp per row, 8 rows/block ----------------------
__global__ void ln_kernel(const float* __restrict__ xin,
                          const float* __restrict__ gamma,
                          const float* __restrict__ beta, int src) {
    int warp = threadIdx.x >> 5, lane = threadIdx.x & 31;
    int r = blockIdx.x*8 + warp;
    const float* in = src ? g_x1 : xin;
    const float4* p = (const float4*)&in[(size_t)r*CCH];
    float4 v0 = p[lane];
    float4 v1 = p[lane + 32];

    float s = v0.x+v0.y+v0.z+v0.w + v1.x+v1.y+v1.z+v1.w;
    #pragma unroll
    for (int o = 16; o; o >>= 1) s += __shfl_xor_sync(0xffffffffu, s, o);
    float mu = s * (1.f/256.f);

    float d0x=v0.x-mu, d0y=v0.y-mu, d0z=v0.z-mu, d0w=v0.w-mu;
    float d1x=v1.x-mu, d1y=v1.y-mu, d1z=v1.z-mu, d1w=v1.w-mu;
    float q = d0x*d0x+d0y*d0y+d0z*d0z+d0w*d0w + d1x*d1x+d1y*d1y+d1z*d1z+d1w*d1w;
    #pragma unroll
    for (int o = 16; o; o >>= 1) q += __shfl_xor_sync(0xffffffffu, q, o);
    float inv = rsqrtf(q * (1.f/256.f) + 1e-5f);

    const float4* gp = (const float4*)gamma;
    const float4* bp = (const float4*)beta;
    float4 g0 = gp[lane], g1v = gp[lane+32];
    float4 b0 = bp[lane], b1v = bp[lane+32];

    __half2 h0 = __floats2half2_rn(d0x*inv*g0.x + b0.x, d0y*inv*g0.y + b0.y);
    __half2 h1 = __floats2half2_rn(d0z*inv*g0.z + b0.z, d0w*inv*g0.w + b0.w);
    __half2 h2 = __floats2half2_rn(d1x*inv*g1v.x + b1v.x, d1y*inv*g1v.y + b1v.y);
    __half2 h3 = __floats2half2_rn(d1z*inv*g1v.z + b1v.z, d1w*inv*g1v.w + b1v.w);

    __half* outp = &g_xnh[(size_t)r*CCH];
    ((uint2*)outp)[lane]      = make_uint2(*(uint32_t*)&h0, *(uint32_t*)&h1);
    ((uint2*)outp)[lane + 32] = make_uint2(*(uint32_t*)&h2, *(uint32_t*)&h3);
}

// ---------------- Windowed attention: transposed layouts, float4 tile loads --
#define QTS 60     // qt/kt row stride (floats): float4-aligned (240B)
#define PTS 56     // pt row stride: float4-aligned (224B)
#define VTS 36     // vs row stride: float4-aligned (144B)
__global__ void attn_kernel() {
    __shared__ float qt[HD][QTS];     // qt[d][r]
    __shared__ float kt[HD][QTS];     // kt[d][m]
    __shared__ float vs[NWT][VTS];    // vs[m][d]
    __shared__ float pt[NWT][PTS];    // pt[m][r]  (scores/probs, transposed)

    int blk  = blockIdx.x;
    int head = blk & 7;
    int Bidx = blk >> 3;
    size_t base = (size_t)blk * NWT * HD;
    int tid = threadIdx.x;
    int lane = tid & 31, wid = tid >> 5;

    const __half2* qp = (const __half2*)&g_q[base];
    const __half2* kp = (const __half2*)&g_k[base];
    const __half2* vp = (const __half2*)&g_v[base];
    for (int i = tid; i < NWT*16; i += 256) {
        int r = i >> 4, d2 = (i & 15) * 2;
        float2 f;
        f = __half22float2(qp[i]); qt[d2][r] = f.x; qt[d2+1][r] = f.y;
        f = __half22float2(kp[i]); kt[d2][r] = f.x; kt[d2+1][r] = f.y;
        f = __half22float2(vp[i]); *(float2*)&vs[r][d2] = f;
    }
    __syncthreads();

    // ---- QK^T: 169 threads, 4x4 tiles, 2x LDS.128 per d ---------------------
    if (tid < 169) {
        int r0 = (tid / 13) * 4, m0 = (tid % 13) * 4;
        float acc[4][4];
        #pragma unroll
        for (int i = 0; i < 4; i++)
            #pragma unroll
            for (int j = 0; j < 4; j++) acc[i][j] = 0.f;
        #pragma unroll 4
        for (int d = 0; d < HD; d++) {
            float4 qv4 = *(const float4*)&qt[d][r0];
            float4 kv4 = *(const float4*)&kt[d][m0];
            float qv[4] = {qv4.x, qv4.y, qv4.z, qv4.w};
            float kv[4] = {kv4.x, kv4.y, kv4.z, kv4.w};
            #pragma unroll
            for (int i = 0; i < 4; i++)
                #pragma unroll
                for (int j = 0; j < 4; j++) acc[i][j] += qv[i]*kv[j];
        }
        #pragma unroll
        for (int i = 0; i < 4; i++) {
            int r = r0 + i;
            if (r < NWT) {
                int rq = r/GW, rr = r%GW;
                #pragma unroll
                for (int j = 0; j < 4; j++) {
                    int m = m0 + j;
                    if (m < NWT) {
                        int dh = rq - m/GW + 6;
                        int dw = rr - m%GW + 6;
                        pt[m][r] = acc[i][j] + g_pos[(dh*13 + dw)*NHH + head];
                    }
                }
            }
        }
    }
    __syncthreads();

    // ---- softmax over m (pt columns), warp-parallel over rows r -------------
    for (int r = wid; r < NWT; r += 8) {
        float v0 = pt[lane][r];
        float v1 = (lane < NWT - 32) ? pt[lane + 32][r] : -1e30f;
        float mx = fmaxf(v0, v1);
        #pragma unroll
        for (int o = 16; o; o >>= 1) mx = fmaxf(mx, __shfl_xor_sync(0xffffffffu, mx, o));
        float e0 = __expf(v0 - mx);
        float e1 = (lane < NWT - 32) ? __expf(v1 - mx) : 0.f;
        float s = e0 + e1;
        #pragma unroll
        for (int o = 16; o; o >>= 1) s += __shfl_xor_sync(0xffffffffu, s, o);
        float inv = 1.f / s;
        pt[lane][r] = e0 * inv;
        if (lane < NWT - 32) pt[lane + 32][r] = e1 * inv;
    }
    __syncthreads();

    // ---- P*V: 104 threads, 4x4 tiles, 2x LDS.128 per m ----------------------
    if (tid < 104) {
        int r0 = (tid >> 3) * 4, d0 = (tid & 7) * 4;
        float acc[4][4];
        #pragma unroll
        for (int i = 0; i < 4; i++)
            #pragma unroll
            for (int j = 0; j < 4; j++) acc[i][j] = 0.f;
        #pragma unroll 7
        for (int m = 0; m < NWT; m++) {
            float4 pv4 = *(const float4*)&pt[m][r0];
            float4 vv4 = *(const float4*)&vs[m][d0];
            float pv[4] = {pv4.x, pv4.y, pv4.z, pv4.w};
            float vv[4] = {vv4.x, vv4.y, vv4.z, vv4.w};
            #pragma unroll
            for (int i = 0; i < 4; i++)
                #pragma unroll
                for (int j = 0; j < 4; j++) acc[i][j] += pv[i]*vv[j];
        }
        #pragma unroll
        for (int i = 0; i < 4; i++) {
            int r = r0 + i;
            if (r < NWT) {
                size_t o = ((size_t)Bidx*NWT + r)*CCH + head*HD + d0;
                *(__half2*)&g_awinh[o]     = __floats2half2_rn(acc[i][0], acc[i][1]);
                *(__half2*)&g_awinh[o + 2] = __floats2half2_rn(acc[i][2], acc[i][3]);
            }
        }
    }
}

// ---------------- launch ----------------------------------------------------
extern "C" void kernel_launch(void* const* d_in, const int* in_sizes, int n_in,
                              void* d_out, int out_size) {
    const float* x        = (const float*)d_in[0];
    const float* norm1_g  = (const float*)d_in[1];
    const float* norm1_b  = (const float*)d_in[2];
    const float* qkv_w    = (const float*)d_in[3];
    const float* qkv_b    = (const float*)d_in[4];
    const float* proj_w   = (const float*)d_in[5];
    const float* proj_b   = (const float*)d_in[6];
    const float* pos_pw   = (const float*)d_in[7];
    const float* pos_pb   = (const float*)d_in[8];
    const float* p1g      = (const float*)d_in[9];
    const float* p1b      = (const float*)d_in[10];
    const float* p1w      = (const float*)d_in[11];
    const float* p1wb     = (const float*)d_in[12];
    const float* p2g      = (const float*)d_in[13];
    const float* p2b      = (const float*)d_in[14];
    const float* p2w      = (const float*)d_in[15];
    const float* p2wb     = (const float*)d_in[16];
    const float* p3g      = (const float*)d_in[17];
    const float* p3b      = (const float*)d_in[18];
    const float* p3w      = (const float*)d_in[19];
    const float* p3wb     = (const float*)d_in[20];
    const float* norm2_g  = (const float*)d_in[21];
    const float* norm2_b  = (const float*)d_in[22];
    const float* fc1_w    = (const float*)d_in[23];
    const float* fc1_b    = (const float*)d_in[24];
    const float* fc2_w    = (const float*)d_in[25];
    const float* fc2_b    = (const float*)d_in[26];
    float* out = (float*)d_out;

    cudaFuncSetAttribute(gemm_mma<0,768,256>,  cudaFuncAttributeMaxDynamicSharedMemorySize, SMEM_TOT);
    cudaFuncSetAttribute(gemm_mma<1,256,256>,  cudaFuncAttributeMaxDynamicSharedMemorySize, SMEM_TOT);
    cudaFuncSetAttribute(gemm_mma<2,1024,256>, cudaFuncAttributeMaxDynamicSharedMemorySize, SMEM_TOT);
    cudaFuncSetAttribute(gemm_mma<3,256,1024>, cudaFuncAttributeMaxDynamicSharedMemorySize, SMEM_TOT);

    pos_mlp_kernel<<<1, 192>>>(pos_pw, pos_pb, p1g, p1b, p1w, p1wb,
                               p2g, p2b, p2w, p2wb, p3g, p3b, p3w, p3wb);
    ln_kernel<<<ROWS/8, 256>>>(x, norm1_g, norm1_b, 0);
    wsplit_kernel<<<(256*768+255)/256, 256>>>(qkv_w, 256, 768, WOFF_QKV);
    gemm_mma<0,768,256><<<dim3(6, ROWS/128), 256, SMEM_TOT>>>(WOFF_QKV, qkv_b, nullptr, nullptr);
    wsplit_kernel<<<(256*256+255)/256, 256>>>(proj_w, 256, 256, WOFF_PROJ);
    attn_kernel<<<BWIN*NHH, 256>>>();
    gemm_mma<1,256,256><<<dim3(2, ROWS/128), 256, SMEM_TOT>>>(WOFF_PROJ, proj_b, x, nullptr);
    wsplit_kernel<<<(256*1024+255)/256, 256>>>(fc1_w, 256, 1024, WOFF_FC1);
    ln_kernel<<<ROWS/8, 256>>>(nullptr, norm2_g, norm2_b, 1);
    gemm_mma<2,1024,256><<<dim3(8, ROWS/128), 256, SMEM_TOT>>>(WOFF_FC1, fc1_b, nullptr, nullptr);
    wsplit_kernel<<<(1024*256+255)/256, 256>>>(fc2_w, 1024, 256, WOFF_FC2);
    gemm_mma<3,256,1024><<<dim3(2, ROWS/128), 256, SMEM_TOT>>>(WOFF_FC2, fc2_b, nullptr, out);
}

// round 13
// speedup vs baseline: 1.5780x; 1.0786x over previous
#include <cuda_runtime.h>
#include <cuda_fp16.h>
#include <math.h>
#include <stdint.h>

#define BB    32
#define HRESD 56
#define WRESD 56
#define CCH   256
#define LLEN  (HRESD*WRESD)          // 3136
#define ROWS  (BB*LLEN)              // 100352
#define NHH   8
#define HD    32
#define GW    7
#define NWT   49
#define NWIN  64
#define BWIN  (BB*NWIN)              // 2048
#define HID   1024
#define QSCALE 0.17677669529663687f

// ---------------- scratch ---------------------------------------------------
__device__ __align__(128) __half g_xnh [(size_t)ROWS*CCH];   // LN out (fp16)
__device__ __align__(128) __half g_awinh[(size_t)ROWS*CCH];  // attn out (fp16)
__device__ __align__(128) __half g_hidh[(size_t)ROWS*HID];   // gelu out (fp16)
__device__ __align__(128) __half g_wth [786432];             // weights fp16, transposed
__device__ __align__(128) __half g_q   [(size_t)BWIN*NHH*NWT*HD];
__device__ __align__(128) __half g_k   [(size_t)BWIN*NHH*NWT*HD];
__device__ __align__(128) __half g_v   [(size_t)BWIN*NHH*NWT*HD];
__device__ float g_x1  [(size_t)ROWS*CCH];
__device__ float g_pos [169*NHH];

#define WOFF_QKV  0
#define WOFF_PROJ 196608
#define WOFF_FC1  262144
#define WOFF_FC2  524288

// ---------------- helpers ----------------------------------------------------
__device__ __forceinline__ uint32_t smem_u32(const void* p) {
    uint32_t a;
    asm("{ .reg .u64 t; cvta.to.shared.u64 t, %1; cvt.u32.u64 %0, t; }" : "=r"(a) : "l"(p));
    return a;
}
__device__ __forceinline__ void ldsm4(uint32_t* r, uint32_t addr) {
    asm volatile("ldmatrix.sync.aligned.m8n8.x4.shared.b16 {%0,%1,%2,%3}, [%4];"
                 : "=r"(r[0]), "=r"(r[1]), "=r"(r[2]), "=r"(r[3]) : "r"(addr));
}
__device__ __forceinline__ void mma16816(float* c, const uint32_t* a, const uint32_t* b) {
    asm volatile("mma.sync.aligned.m16n8k16.row.col.f32.f16.f16.f32 "
                 "{%0,%1,%2,%3}, {%4,%5,%6,%7}, {%8,%9}, {%0,%1,%2,%3};"
                 : "+f"(c[0]), "+f"(c[1]), "+f"(c[2]), "+f"(c[3])
                 : "r"(a[0]), "r"(a[1]), "r"(a[2]), "r"(a[3]), "r"(b[0]), "r"(b[1]));
}
#define CP16(dst, src) asm volatile("cp.async.cg.shared.global [%0], [%1], 16;" :: "r"(dst), "l"(src))
#define CP_COMMIT()    asm volatile("cp.async.commit_group;")
#define CP_WAIT0()     asm volatile("cp.async.wait_group 0;")
#define CP_WAIT1()     asm volatile("cp.async.wait_group 1;")

#define SSTR    72
#define ARR_B   (128*SSTR*2)           // 18432 B
#define STAGE_B (2*ARR_B)              // Ah + Bh = 36864 B
#define SMEM_TOT (3*STAGE_B)           // 110592 B -> 2 CTAs/SM

// ---------------- 3-stage fp16 GEMM: 128x128 tile, BK=64 (1032-proven) -------
// EPI: 0=QKV  1=PROJ  2=FC1+GELU  3=FC2+res
template<int EPI, int NC, int KC>
__global__ __launch_bounds__(256, 2) void gemm_mma(size_t woff,
                                                   const float* __restrict__ bias,
                                                   const float* __restrict__ X,
                                                   float* __restrict__ Out) {
    extern __shared__ char smc[];
    uint32_t smb = smem_u32(smc);

    const __half* A_g  = (EPI == 1) ? g_awinh : (EPI == 3 ? g_hidh : g_xnh);
    const __half* Bh_g = g_wth + woff;

    int tid  = threadIdx.x;
    int lane = tid & 31, wid = tid >> 5;
    int warpM = wid & 3, warpN = wid >> 2;        // 4 x 2 warp grid, 32x64 each
    int rbase = blockIdx.y * 128;
    int cbase = blockIdx.x * 128;

    float acc[2][8][4];
    #pragma unroll
    for (int mi = 0; mi < 2; mi++)
        #pragma unroll
        for (int nj = 0; nj < 8; nj++)
            #pragma unroll
            for (int e = 0; e < 4; e++) acc[mi][nj][e] = 0.f;

    const int arow = tid >> 3;
    const int kc8  = (tid & 7) * 8;

    auto issueTile = [&](int t) {
        int kt = t * 64;
        uint32_t sb = smb + (uint32_t)((t % 3) * STAGE_B);
        #pragma unroll
        for (int u = 0; u < 4; u++) {
            int row = u*32 + arow;
            CP16(sb + (uint32_t)((row*SSTR + kc8)*2),
                 A_g + (size_t)(rbase + row)*KC + kt + kc8);
        }
        #pragma unroll
        for (int u = 0; u < 4; u++) {
            int row = u*32 + arow;
            CP16(sb + (uint32_t)(ARR_B + (row*SSTR + kc8)*2),
                 Bh_g + (size_t)(cbase + row)*KC + kt + kc8);
        }
    };

    const int T = KC / 64;
    issueTile(0); CP_COMMIT();
    issueTile(1); CP_COMMIT();

    for (int t = 0; t < T; t++) {
        if (t + 1 < T) { CP_WAIT1(); } else { CP_WAIT0(); }
        __syncthreads();
        if (t + 2 < T) { issueTile(t + 2); CP_COMMIT(); }

        uint32_t ahb = smb + (uint32_t)((t % 3) * STAGE_B);
        uint32_t bhb = ahb + ARR_B;

        #pragma unroll
        for (int k0 = 0; k0 < 64; k0 += 16) {
            uint32_t a_h[2][4];
            #pragma unroll
            for (int mi = 0; mi < 2; mi++) {
                int row = warpM*32 + mi*16 + (lane & 15);
                int col = k0 + ((lane & 16) >> 1);
                ldsm4(a_h[mi], ahb + (uint32_t)(row*SSTR + col)*2);
            }
            #pragma unroll
            for (int j = 0; j < 4; j++) {
                int row = warpN*64 + j*16 + (lane & 7) + ((lane & 16) >> 1);
                int col = k0 + (lane & 8);
                uint32_t r[4];
                ldsm4(r, bhb + (uint32_t)(row*SSTR + col)*2);
                mma16816(acc[0][j*2],   a_h[0], r);
                mma16816(acc[0][j*2+1], a_h[0], r+2);
                mma16816(acc[1][j*2],   a_h[1], r);
                mma16816(acc[1][j*2+1], a_h[1], r+2);
            }
        }
    }

    // ---- epilogue: per-row precompute, paired wide stores -------------------
    #pragma unroll
    for (int mi = 0; mi < 2; mi++)
        #pragma unroll
        for (int eh = 0; eh < 2; eh++) {
            int row = rbase + warpM*32 + mi*16 + (lane >> 2) + eh*8;

            if (EPI == 0) {
                int b  = row / LLEN, l = row % LLEN;
                int hh = l / WRESD, wc = l % WRESD;
                int wh = hh / GW, ii = hh % GW;
                int wn = wc / GW, jj = wc % GW;
                int Bidx = b*NWIN + wh*8 + wn;
                int n = ii*GW + jj;
                size_t rb = (size_t)Bidx*(NHH*NWT*HD) + (size_t)n*HD;
                #pragma unroll
                for (int nj = 0; nj < 8; nj++) {
                    int c = cbase + warpN*64 + nj*8 + (lane & 3)*2;
                    float2 bv = *(const float2*)&bias[c];
                    float v0 = acc[mi][nj][eh*2+0] + bv.x;
                    float v1 = acc[mi][nj][eh*2+1] + bv.y;
                    int sect = c >> 8;
                    int head = (c >> 5) & 7;
                    int d    = c & 31;
                    size_t idx = rb + (size_t)head*(NWT*HD) + d;
                    if (sect == 0)
                        *(__half2*)&g_q[idx] = __floats2half2_rn(v0*QSCALE, v1*QSCALE);
                    else if (sect == 1)
                        *(__half2*)&g_k[idx] = __floats2half2_rn(v0, v1);
                    else
                        *(__half2*)&g_v[idx] = __floats2half2_rn(v0, v1);
                }
            } else if (EPI == 1) {
                int Bidx = row / NWT, n = row % NWT;
                int b  = Bidx / NWIN, wi = Bidx % NWIN;
                int wh = wi / 8, wn = wi % 8;
                int ii = n / GW, jj = n % GW;
                int l  = (wh*GW + ii)*WRESD + wn*GW + jj;
                size_t rowoff = ((size_t)b*LLEN + l)*CCH;
                #pragma unroll
                for (int nj = 0; nj < 8; nj++) {
                    int c = cbase + warpN*64 + nj*8 + (lane & 3)*2;
                    float2 bv = *(const float2*)&bias[c];
                    float2 xv = *(const float2*)&X[rowoff + c];
                    *(float2*)&g_x1[rowoff + c] =
                        make_float2(xv.x + acc[mi][nj][eh*2+0] + bv.x,
                                    xv.y + acc[mi][nj][eh*2+1] + bv.y);
                }
            } else if (EPI == 2) {
                size_t rowoff = (size_t)row*HID;
                #pragma unroll
                for (int nj = 0; nj < 8; nj++) {
                    int c = cbase + warpN*64 + nj*8 + (lane & 3)*2;
                    float2 bv = *(const float2*)&bias[c];
                    float v0 = acc[mi][nj][eh*2+0] + bv.x;
                    float v1 = acc[mi][nj][eh*2+1] + bv.y;
                    float g0 = 0.5f*v0*(1.f + erff(v0*0.70710678118654752f));
                    float g1 = 0.5f*v1*(1.f + erff(v1*0.70710678118654752f));
                    *(__half2*)&g_hidh[rowoff + c] = __floats2half2_rn(g0, g1);
                }
            } else {
                size_t rowoff = (size_t)row*CCH;
                #pragma unroll
                for (int nj = 0; nj < 8; nj++) {
                    int c = cbase + warpN*64 + nj*8 + (lane & 3)*2;
                    float2 bv = *(const float2*)&bias[c];
                    float2 xv = *(const float2*)&g_x1[rowoff + c];
                    *(float2*)&Out[rowoff + c] =
                        make_float2(xv.x + acc[mi][nj][eh*2+0] + bv.x,
                                    xv.y + acc[mi][nj][eh*2+1] + bv.y);
                }
            }
        }
}

// ---------------- DynamicPosBias MLP (device fn) -----------------------------
__device__ __forceinline__ void pos_stage(float* t, const float* g, const float* b,
                                          const float* w, const float* wb, int outn) {
    float mu = 0.f;
    #pragma unroll
    for (int p = 0; p < 16; p++) mu += t[p];
    mu *= (1.f/16.f);
    float var = 0.f;
    #pragma unroll
    for (int p = 0; p < 16; p++) { float d = t[p]-mu; var += d*d; }
    var *= (1.f/16.f);
    float inv = rsqrtf(var + 1e-5f);
    float u[16];
    #pragma unroll
    for (int p = 0; p < 16; p++) {
        float z = (t[p]-mu)*inv*g[p] + b[p];
        u[p] = fmaxf(z, 0.f);
    }
    for (int q = 0; q < outn; q++) {
        float s = wb[q];
        #pragma unroll
        for (int p = 0; p < 16; p++) s += u[p]*w[p*outn + q];
        t[q] = s;
    }
}

// ---------------- fused prep: 4 weight transposes + pos MLP ------------------
// grid = 3073 blocks of 256; block 3072 runs the pos MLP.
__global__ void prep_kernel(const float* __restrict__ w_qkv,
                            const float* __restrict__ w_proj,
                            const float* __restrict__ w_fc1,
                            const float* __restrict__ w_fc2,
                            const float* pw, const float* pb,
                            const float* g1, const float* b1, const float* w1, const float* wb1,
                            const float* g2, const float* b2, const float* w2, const float* wb2,
                            const float* g3, const float* b3, const float* w3, const float* wb3) {
    if (blockIdx.x == 3072) {
        int i = threadIdx.x;
        if (i >= 169) return;
        float bh = (float)(i/13 - 6);
        float bw = (float)(i%13 - 6);
        float t[16];
        #pragma unroll
        for (int p = 0; p < 16; p++) t[p] = bh*pw[p] + bw*pw[16+p] + pb[p];
        pos_stage(t, g1, b1, w1, wb1, 16);
        pos_stage(t, g2, b2, w2, wb2, 16);
        pos_stage(t, g3, b3, w3, wb3, NHH);
        #pragma unroll
        for (int h = 0; h < NHH; h++) g_pos[i*NHH + h] = t[h];
        return;
    }
    int idx = blockIdx.x*256 + threadIdx.x;   // == destination offset in g_wth
    const float* w; int K, N, off;
    if (idx < WOFF_PROJ)      { w = w_qkv;  K = 256;  N = 768;  off = WOFF_QKV;  }
    else if (idx < WOFF_FC1)  { w = w_proj; K = 256;  N = 256;  off = WOFF_PROJ; }
    else if (idx < WOFF_FC2)  { w = w_fc1;  K = 256;  N = 1024; off = WOFF_FC1;  }
    else                      { w = w_fc2;  K = 1024; N = 256;  off = WOFF_FC2;  }
    int local = idx - off;
    int n = local / K, k = local - n*K;
    g_wth[idx] = __float2half_rn(w[(size_t)k*N + n]);
}

// ---------------- LayerNorm: warp per row, 8 rows/block ----------------------
__global__ void ln_kernel(const float* __restrict__ xin,
                          const float* __restrict__ gamma,
                          const float* __restrict__ beta, int src) {
    int warp = threadIdx.x >> 5, lane = threadIdx.x & 31;
    int r = blockIdx.x*8 + warp;
    const float* in = src ? g_x1 : xin;
    const float4* p = (const float4*)&in[(size_t)r*CCH];
    float4 v0 = p[lane];
    float4 v1 = p[lane + 32];

    float s = v0.x+v0.y+v0.z+v0.w + v1.x+v1.y+v1.z+v1.w;
    #pragma unroll
    for (int o = 16; o; o >>= 1) s += __shfl_xor_sync(0xffffffffu, s, o);
    float mu = s * (1.f/256.f);

    float d0x=v0.x-mu, d0y=v0.y-mu, d0z=v0.z-mu, d0w=v0.w-mu;
    float d1x=v1.x-mu, d1y=v1.y-mu, d1z=v1.z-mu, d1w=v1.w-mu;
    float q = d0x*d0x+d0y*d0y+d0z*d0z+d0w*d0w + d1x*d1x+d1y*d1y+d1z*d1z+d1w*d1w;
    #pragma unroll
    for (int o = 16; o; o >>= 1) q += __shfl_xor_sync(0xffffffffu, q, o);
    float inv = rsqrtf(q * (1.f/256.f) + 1e-5f);

    const float4* gp = (const float4*)gamma;
    const float4* bp = (const float4*)beta;
    float4 g0 = gp[lane], g1v = gp[lane+32];
    float4 b0 = bp[lane], b1v = bp[lane+32];

    __half2 h0 = __floats2half2_rn(d0x*inv*g0.x + b0.x, d0y*inv*g0.y + b0.y);
    __half2 h1 = __floats2half2_rn(d0z*inv*g0.z + b0.z, d0w*inv*g0.w + b0.w);
    __half2 h2 = __floats2half2_rn(d1x*inv*g1v.x + b1v.x, d1y*inv*g1v.y + b1v.y);
    __half2 h3 = __floats2half2_rn(d1z*inv*g1v.z + b1v.z, d1w*inv*g1v.w + b1v.w);

    __half* outp = &g_xnh[(size_t)r*CCH];
    ((uint2*)outp)[lane]      = make_uint2(*(uint32_t*)&h0, *(uint32_t*)&h1);
    ((uint2*)outp)[lane + 32] = make_uint2(*(uint32_t*)&h2, *(uint32_t*)&h3);
}

// ---------------- Windowed attention: 1032-proven (4x4 tiles, stride-33) -----
#define QR 52                      // 49 rounded up to 4
__global__ void attn_kernel() {
    __shared__ float qs[QR][33];   // stride 33 floats: conflict-free row access
    __shared__ float ks[QR][33];
    __shared__ float vs[NWT][33];
    __shared__ float at[QR][50];

    int blk  = blockIdx.x;
    int head = blk & 7;
    int Bidx = blk >> 3;
    size_t base = (size_t)blk * NWT * HD;
    int tid = threadIdx.x;
    int lane = tid & 31, wid = tid >> 5;

    const __half2* qp = (const __half2*)&g_q[base];
    const __half2* kp = (const __half2*)&g_k[base];
    const __half2* vp = (const __half2*)&g_v[base];
    for (int i = tid; i < NWT*16; i += 256) {
        int r = i >> 4, d2 = (i & 15) * 2;
        float2 f;
        f = __half22float2(qp[i]); qs[r][d2] = f.x; qs[r][d2+1] = f.y;
        f = __half22float2(kp[i]); ks[r][d2] = f.x; ks[r][d2+1] = f.y;
        f = __half22float2(vp[i]); vs[r][d2] = f.x; vs[r][d2+1] = f.y;
    }
    // zero the 3 padding rows (49..51)
    if (tid < 96) {
        int r = 49 + tid/32, d = tid & 31;
        qs[r][d] = 0.f; ks[r][d] = 0.f;
    }
    __syncthreads();

    // ---- QK^T: 13x13 tiles of 4x4 -------------------------------------------
    if (tid < 169) {
        int rg = tid / 13, mg = tid % 13;
        int r0 = rg*4, m0 = mg*4;
        float acc[4][4];
        #pragma unroll
        for (int i = 0; i < 4; i++)
            #pragma unroll
            for (int j = 0; j < 4; j++) acc[i][j] = 0.f;
        #pragma unroll 4
        for (int d = 0; d < HD; d++) {
            float qv[4], kv[4];
            #pragma unroll
            for (int i = 0; i < 4; i++) qv[i] = qs[r0+i][d];
            #pragma unroll
            for (int j = 0; j < 4; j++) kv[j] = ks[m0+j][d];
            #pragma unroll
            for (int i = 0; i < 4; i++)
                #pragma unroll
                for (int j = 0; j < 4; j++) acc[i][j] += qv[i]*kv[j];
        }
        #pragma unroll
        for (int i = 0; i < 4; i++) {
            int r = r0 + i;
            if (r < NWT) {
                int rq = r/GW, rr = r%GW;
                #pragma unroll
                for (int j = 0; j < 4; j++) {
                    int m = m0 + j;
                    if (m < NWT) {
                        int dh = rq - m/GW + 6;
                        int dw = rr - m%GW + 6;
                        at[r][m] = acc[i][j] + g_pos[(dh*13 + dw)*NHH + head];
                    }
                }
            }
        }
    }
    __syncthreads();

    // ---- softmax: warp-parallel over rows -----------------------------------
    for (int r = wid; r < NWT; r += 8) {
        float v0 = at[r][lane];
        float v1 = (lane < NWT - 32) ? at[r][lane + 32] : -1e30f;
        float mx = fmaxf(v0, v1);
        #pragma unroll
        for (int o = 16; o; o >>= 1) mx = fmaxf(mx, __shfl_xor_sync(0xffffffffu, mx, o));
        float e0 = __expf(v0 - mx);
        float e1 = (lane < NWT - 32) ? __expf(v1 - mx) : 0.f;
        float s = e0 + e1;
        #pragma unroll
        for (int o = 16; o; o >>= 1) s += __shfl_xor_sync(0xffffffffu, s, o);
        float inv = 1.f / s;
        at[r][lane] = e0 * inv;
        if (lane < NWT - 32) at[r][lane + 32] = e1 * inv;
    }
    // zero padding rows of at so PV on rows 49..51 reads finite values
    if (tid < 3*NWT) {
        int r = 49 + tid/NWT, m = tid % NWT;
        at[r][m] = 0.f;
    }
    __syncthreads();

    // ---- P*V: 13x8 tiles of 4 rows x 4 cols ---------------------------------
    if (tid < 104) {
        int rg = tid >> 3, dg = tid & 7;
        int r0 = rg*4, d0 = dg*4;
        float acc[4][4];
        #pragma unroll
        for (int i = 0; i < 4; i++)
            #pragma unroll
            for (int j = 0; j < 4; j++) acc[i][j] = 0.f;
        #pragma unroll 7
        for (int m = 0; m < NWT; m++) {
            float av[4], vv[4];
            #pragma unroll
            for (int i = 0; i < 4; i++) av[i] = at[r0+i][m];
            #pragma unroll
            for (int j = 0; j < 4; j++) vv[j] = vs[m][d0+j];
            #pragma unroll
            for (int i = 0; i < 4; i++)
                #pragma unroll
                for (int j = 0; j < 4; j++) acc[i][j] += av[i]*vv[j];
        }
        #pragma unroll
        for (int i = 0; i < 4; i++) {
            int r = r0 + i;
            if (r < NWT) {
                size_t o = ((size_t)Bidx*NWT + r)*CCH + head*HD + d0;
                *(__half2*)&g_awinh[o]     = __floats2half2_rn(acc[i][0], acc[i][1]);
                *(__half2*)&g_awinh[o + 2] = __floats2half2_rn(acc[i][2], acc[i][3]);
            }
        }
    }
}

// ---------------- launch ----------------------------------------------------
extern "C" void kernel_launch(void* const* d_in, const int* in_sizes, int n_in,
                              void* d_out, int out_size) {
    const float* x        = (const float*)d_in[0];
    const float* norm1_g  = (const float*)d_in[1];
    const float* norm1_b  = (const float*)d_in[2];
    const float* qkv_w    = (const float*)d_in[3];
    const float* qkv_b    = (const float*)d_in[4];
    const float* proj_w   = (const float*)d_in[5];
    const float* proj_b   = (const float*)d_in[6];
    const float* pos_pw   = (const float*)d_in[7];
    const float* pos_pb   = (const float*)d_in[8];
    const float* p1g      = (const float*)d_in[9];
    const float* p1b      = (const float*)d_in[10];
    const float* p1w      = (const float*)d_in[11];
    const float* p1wb     = (const float*)d_in[12];
    const float* p2g      = (const float*)d_in[13];
    const float* p2b      = (const float*)d_in[14];
    const float* p2w      = (const float*)d_in[15];
    const float* p2wb     = (const float*)d_in[16];
    const float* p3g      = (const float*)d_in[17];
    const float* p3b      = (const float*)d_in[18];
    const float* p3w      = (const float*)d_in[19];
    const float* p3wb     = (const float*)d_in[20];
    const float* norm2_g  = (const float*)d_in[21];
    const float* norm2_b  = (const float*)d_in[22];
    const float* fc1_w    = (const float*)d_in[23];
    const float* fc1_b    = (const float*)d_in[24];
    const float* fc2_w    = (const float*)d_in[25];
    const float* fc2_b    = (const float*)d_in[26];
    float* out = (float*)d_out;

    cudaFuncSetAttribute(gemm_mma<0,768,256>,  cudaFuncAttributeMaxDynamicSharedMemorySize, SMEM_TOT);
    cudaFuncSetAttribute(gemm_mma<1,256,256>,  cudaFuncAttributeMaxDynamicSharedMemorySize, SMEM_TOT);
    cudaFuncSetAttribute(gemm_mma<2,1024,256>, cudaFuncAttributeMaxDynamicSharedMemorySize, SMEM_TOT);
    cudaFuncSetAttribute(gemm_mma<3,256,1024>, cudaFuncAttributeMaxDynamicSharedMemorySize, SMEM_TOT);

    // launch order: prep(0), ln1(1), qkv(2), attn(3) -> ncu profiles R9 attn
    prep_kernel<<<3073, 256>>>(qkv_w, proj_w, fc1_w, fc2_w,
                               pos_pw, pos_pb, p1g, p1b, p1w, p1wb,
                               p2g, p2b, p2w, p2wb, p3g, p3b, p3w, p3wb);
    ln_kernel<<<ROWS/8, 256>>>(x, norm1_g, norm1_b, 0);
    gemm_mma<0,768,256><<<dim3(6, ROWS/128), 256, SMEM_TOT>>>(WOFF_QKV, qkv_b, nullptr, nullptr);
    attn_kernel<<<BWIN*NHH, 256>>>();
    gemm_mma<1,256,256><<<dim3(2, ROWS/128), 256, SMEM_TOT>>>(WOFF_PROJ, proj_b, x, nullptr);
    ln_kernel<<<ROWS/8, 256>>>(nullptr, norm2_g, norm2_b, 1);
    gemm_mma<2,1024,256><<<dim3(8, ROWS/128), 256, SMEM_TOT>>>(WOFF_FC1, fc1_b, nullptr, nullptr);
    gemm_mma<3,256,1024><<<dim3(2, ROWS/128), 256, SMEM_TOT>>>(WOFF_FC2, fc2_b, nullptr, out);
}

// round 15
// speedup vs baseline: 1.6143x; 1.0230x over previous
#include <cuda_runtime.h>
#include <cuda_fp16.h>
#include <math.h>
#include <stdint.h>

#define BB    32
#define HRESD 56
#define WRESD 56
#define CCH   256
#define LLEN  (HRESD*WRESD)          // 3136
#define ROWS  (BB*LLEN)              // 100352
#define NHH   8
#define HD    32
#define GW    7
#define NWT   49
#define NWIN  64
#define BWIN  (BB*NWIN)              // 2048
#define HID   1024
#define QSCALE 0.17677669529663687f

// ---------------- scratch ---------------------------------------------------
__device__ __align__(128) __half g_xnh [(size_t)ROWS*CCH];   // LN out (fp16)
__device__ __align__(128) __half g_awinh[(size_t)ROWS*CCH];  // attn out (fp16)
__device__ __align__(128) __half g_hidh[(size_t)ROWS*HID];   // gelu out (fp16)
__device__ __align__(128) __half g_wth [786432];             // weights fp16, transposed
__device__ __align__(128) __half g_q   [(size_t)BWIN*NHH*NWT*HD];
__device__ __align__(128) __half g_k   [(size_t)BWIN*NHH*NWT*HD];
__device__ __align__(128) __half g_v   [(size_t)BWIN*NHH*NWT*HD];
__device__ float g_x1  [(size_t)ROWS*CCH];
__device__ float g_pos [169*NHH];

#define WOFF_QKV  0
#define WOFF_PROJ 196608
#define WOFF_FC1  262144
#define WOFF_FC2  524288

// ---------------- helpers ----------------------------------------------------
__device__ __forceinline__ uint32_t smem_u32(const void* p) {
    uint32_t a;
    asm("{ .reg .u64 t; cvta.to.shared.u64 t, %1; cvt.u32.u64 %0, t; }" : "=r"(a) : "l"(p));
    return a;
}
__device__ __forceinline__ void ldsm4(uint32_t* r, uint32_t addr) {
    asm volatile("ldmatrix.sync.aligned.m8n8.x4.shared.b16 {%0,%1,%2,%3}, [%4];"
                 : "=r"(r[0]), "=r"(r[1]), "=r"(r[2]), "=r"(r[3]) : "r"(addr));
}
__device__ __forceinline__ void mma16816(float* c, const uint32_t* a, const uint32_t* b) {
    asm volatile("mma.sync.aligned.m16n8k16.row.col.f32.f16.f16.f32 "
                 "{%0,%1,%2,%3}, {%4,%5,%6,%7}, {%8,%9}, {%0,%1,%2,%3};"
                 : "+f"(c[0]), "+f"(c[1]), "+f"(c[2]), "+f"(c[3])
                 : "r"(a[0]), "r"(a[1]), "r"(a[2]), "r"(a[3]), "r"(b[0]), "r"(b[1]));
}
#define CP16(dst, src) asm volatile("cp.async.cg.shared.global [%0], [%1], 16;" :: "r"(dst), "l"(src))
#define CP_COMMIT()    asm volatile("cp.async.commit_group;")
#define CP_WAIT0()     asm volatile("cp.async.wait_group 0;")
#define CP_WAIT1()     asm volatile("cp.async.wait_group 1;")

#define SSTR    72
#define ARR_B   (128*SSTR*2)           // 18432 B
#define STAGE_B (2*ARR_B)              // Ah + Bh = 36864 B
#define SMEM_TOT (3*STAGE_B)           // 110592 B -> 2 CTAs/SM

// ---------------- 3-stage fp16 GEMM: 128x128 tile, BK=64 (1032-proven) -------
// EPI: 0=QKV  1=PROJ  2=FC1+GELU  3=FC2+res
template<int EPI, int NC, int KC>
__global__ __launch_bounds__(256, 2) void gemm_mma(size_t woff,
                                                   const float* __restrict__ bias,
                                                   const float* __restrict__ X,
                                                   float* __restrict__ Out) {
    extern __shared__ char smc[];
    uint32_t smb = smem_u32(smc);

    const __half* A_g  = (EPI == 1) ? g_awinh : (EPI == 3 ? g_hidh : g_xnh);
    const __half* Bh_g = g_wth + woff;

    int tid  = threadIdx.x;
    int lane = tid & 31, wid = tid >> 5;
    int warpM = wid & 3, warpN = wid >> 2;        // 4 x 2 warp grid, 32x64 each
    int rbase = blockIdx.y * 128;
    int cbase = blockIdx.x * 128;

    float acc[2][8][4];
    #pragma unroll
    for (int mi = 0; mi < 2; mi++)
        #pragma unroll
        for (int nj = 0; nj < 8; nj++)
            #pragma unroll
            for (int e = 0; e < 4; e++) acc[mi][nj][e] = 0.f;

    const int arow = tid >> 3;
    const int kc8  = (tid & 7) * 8;

    auto issueTile = [&](int t) {
        int kt = t * 64;
        uint32_t sb = smb + (uint32_t)((t % 3) * STAGE_B);
        #pragma unroll
        for (int u = 0; u < 4; u++) {
            int row = u*32 + arow;
            CP16(sb + (uint32_t)((row*SSTR + kc8)*2),
                 A_g + (size_t)(rbase + row)*KC + kt + kc8);
        }
        #pragma unroll
        for (int u = 0; u < 4; u++) {
            int row = u*32 + arow;
            CP16(sb + (uint32_t)(ARR_B + (row*SSTR + kc8)*2),
                 Bh_g + (size_t)(cbase + row)*KC + kt + kc8);
        }
    };

    const int T = KC / 64;
    issueTile(0); CP_COMMIT();
    issueTile(1); CP_COMMIT();

    for (int t = 0; t < T; t++) {
        if (t + 1 < T) { CP_WAIT1(); } else { CP_WAIT0(); }
        __syncthreads();
        if (t + 2 < T) { issueTile(t + 2); CP_COMMIT(); }

        uint32_t ahb = smb + (uint32_t)((t % 3) * STAGE_B);
        uint32_t bhb = ahb + ARR_B;

        #pragma unroll
        for (int k0 = 0; k0 < 64; k0 += 16) {
            uint32_t a_h[2][4];
            #pragma unroll
            for (int mi = 0; mi < 2; mi++) {
                int row = warpM*32 + mi*16 + (lane & 15);
                int col = k0 + ((lane & 16) >> 1);
                ldsm4(a_h[mi], ahb + (uint32_t)(row*SSTR + col)*2);
            }
            #pragma unroll
            for (int j = 0; j < 4; j++) {
                int row = warpN*64 + j*16 + (lane & 7) + ((lane & 16) >> 1);
                int col = k0 + (lane & 8);
                uint32_t r[4];
                ldsm4(r, bhb + (uint32_t)(row*SSTR + col)*2);
                mma16816(acc[0][j*2],   a_h[0], r);
                mma16816(acc[0][j*2+1], a_h[0], r+2);
                mma16816(acc[1][j*2],   a_h[1], r);
                mma16816(acc[1][j*2+1], a_h[1], r+2);
            }
        }
    }

    // ---- epilogue: per-row precompute, paired wide stores -------------------
    #pragma unroll
    for (int mi = 0; mi < 2; mi++)
        #pragma unroll
        for (int eh = 0; eh < 2; eh++) {
            int row = rbase + warpM*32 + mi*16 + (lane >> 2) + eh*8;

            if (EPI == 0) {
                int b  = row / LLEN, l = row % LLEN;
                int hh = l / WRESD, wc = l % WRESD;
                int wh = hh / GW, ii = hh % GW;
                int wn = wc / GW, jj = wc % GW;
                int Bidx = b*NWIN + wh*8 + wn;
                int n = ii*GW + jj;
                size_t rb = (size_t)Bidx*(NHH*NWT*HD) + (size_t)n*HD;
                #pragma unroll
                for (int nj = 0; nj < 8; nj++) {
                    int c = cbase + warpN*64 + nj*8 + (lane & 3)*2;
                    float2 bv = *(const float2*)&bias[c];
                    float v0 = acc[mi][nj][eh*2+0] + bv.x;
                    float v1 = acc[mi][nj][eh*2+1] + bv.y;
                    int sect = c >> 8;
                    int head = (c >> 5) & 7;
                    int d    = c & 31;
                    size_t idx = rb + (size_t)head*(NWT*HD) + d;
                    if (sect == 0)
                        *(__half2*)&g_q[idx] = __floats2half2_rn(v0*QSCALE, v1*QSCALE);
                    else if (sect == 1)
                        *(__half2*)&g_k[idx] = __floats2half2_rn(v0, v1);
                    else
                        *(__half2*)&g_v[idx] = __floats2half2_rn(v0, v1);
                }
            } else if (EPI == 1) {
                int Bidx = row / NWT, n = row % NWT;
                int b  = Bidx / NWIN, wi = Bidx % NWIN;
                int wh = wi / 8, wn = wi % 8;
                int ii = n / GW, jj = n % GW;
                int l  = (wh*GW + ii)*WRESD + wn*GW + jj;
                size_t rowoff = ((size_t)b*LLEN + l)*CCH;
                #pragma unroll
                for (int nj = 0; nj < 8; nj++) {
                    int c = cbase + warpN*64 + nj*8 + (lane & 3)*2;
                    float2 bv = *(const float2*)&bias[c];
                    float2 xv = *(const float2*)&X[rowoff + c];
                    *(float2*)&g_x1[rowoff + c] =
                        make_float2(xv.x + acc[mi][nj][eh*2+0] + bv.x,
                                    xv.y + acc[mi][nj][eh*2+1] + bv.y);
                }
            } else if (EPI == 2) {
                size_t rowoff = (size_t)row*HID;
                #pragma unroll
                for (int nj = 0; nj < 8; nj++) {
                    int c = cbase + warpN*64 + nj*8 + (lane & 3)*2;
                    float2 bv = *(const float2*)&bias[c];
                    float v0 = acc[mi][nj][eh*2+0] + bv.x;
                    float v1 = acc[mi][nj][eh*2+1] + bv.y;
                    float g0 = 0.5f*v0*(1.f + erff(v0*0.70710678118654752f));
                    float g1 = 0.5f*v1*(1.f + erff(v1*0.70710678118654752f));
                    *(__half2*)&g_hidh[rowoff + c] = __floats2half2_rn(g0, g1);
                }
            } else {
                size_t rowoff = (size_t)row*CCH;
                #pragma unroll
                for (int nj = 0; nj < 8; nj++) {
                    int c = cbase + warpN*64 + nj*8 + (lane & 3)*2;
                    float2 bv = *(const float2*)&bias[c];
                    float2 xv = *(const float2*)&g_x1[rowoff + c];
                    *(float2*)&Out[rowoff + c] =
                        make_float2(xv.x + acc[mi][nj][eh*2+0] + bv.x,
                                    xv.y + acc[mi][nj][eh*2+1] + bv.y);
                }
            }
        }
}

// ---------------- DynamicPosBias MLP (device fn) -----------------------------
__device__ __forceinline__ void pos_stage(float* t, const float* g, const float* b,
                                          const float* w, const float* wb, int outn) {
    float mu = 0.f;
    #pragma unroll
    for (int p = 0; p < 16; p++) mu += t[p];
    mu *= (1.f/16.f);
    float var = 0.f;
    #pragma unroll
    for (int p = 0; p < 16; p++) { float d = t[p]-mu; var += d*d; }
    var *= (1.f/16.f);
    float inv = rsqrtf(var + 1e-5f);
    float u[16];
    #pragma unroll
    for (int p = 0; p < 16; p++) {
        float z = (t[p]-mu)*inv*g[p] + b[p];
        u[p] = fmaxf(z, 0.f);
    }
    for (int q = 0; q < outn; q++) {
        float s = wb[q];
        #pragma unroll
        for (int p = 0; p < 16; p++) s += u[p]*w[p*outn + q];
        t[q] = s;
    }
}

// ---------------- fused prep: 4 weight transposes + pos MLP ------------------
__global__ void prep_kernel(const float* __restrict__ w_qkv,
                            const float* __restrict__ w_proj,
                            const float* __restrict__ w_fc1,
                            const float* __restrict__ w_fc2,
                            const float* pw, const float* pb,
                            const float* g1, const float* b1, const float* w1, const float* wb1,
                            const float* g2, const float* b2, const float* w2, const float* wb2,
                            const float* g3, const float* b3, const float* w3, const float* wb3) {
    if (blockIdx.x == 3072) {
        int i = threadIdx.x;
        if (i >= 169) return;
        float bh = (float)(i/13 - 6);
        float bw = (float)(i%13 - 6);
        float t[16];
        #pragma unroll
        for (int p = 0; p < 16; p++) t[p] = bh*pw[p] + bw*pw[16+p] + pb[p];
        pos_stage(t, g1, b1, w1, wb1, 16);
        pos_stage(t, g2, b2, w2, wb2, 16);
        pos_stage(t, g3, b3, w3, wb3, NHH);
        #pragma unroll
        for (int h = 0; h < NHH; h++) g_pos[i*NHH + h] = t[h];
        return;
    }
    int idx = blockIdx.x*256 + threadIdx.x;   // == destination offset in g_wth
    const float* w; int K, N, off;
    if (idx < WOFF_PROJ)      { w = w_qkv;  K = 256;  N = 768;  off = WOFF_QKV;  }
    else if (idx < WOFF_FC1)  { w = w_proj; K = 256;  N = 256;  off = WOFF_PROJ; }
    else if (idx < WOFF_FC2)  { w = w_fc1;  K = 256;  N = 1024; off = WOFF_FC1;  }
    else                      { w = w_fc2;  K = 1024; N = 256;  off = WOFF_FC2;  }
    int local = idx - off;
    int n = local / K, k = local - n*K;
    g_wth[idx] = __float2half_rn(w[(size_t)k*N + n]);
}

// ---------------- LayerNorm: warp per row, 8 rows/block ----------------------
__global__ void ln_kernel(const float* __restrict__ xin,
                          const float* __restrict__ gamma,
                          const float* __restrict__ beta, int src) {
    int warp = threadIdx.x >> 5, lane = threadIdx.x & 31;
    int r = blockIdx.x*8 + warp;
    const float* in = src ? g_x1 : xin;
    const float4* p = (const float4*)&in[(size_t)r*CCH];
    float4 v0 = p[lane];
    float4 v1 = p[lane + 32];

    float s = v0.x+v0.y+v0.z+v0.w + v1.x+v1.y+v1.z+v1.w;
    #pragma unroll
    for (int o = 16; o; o >>= 1) s += __shfl_xor_sync(0xffffffffu, s, o);
    float mu = s * (1.f/256.f);

    float d0x=v0.x-mu, d0y=v0.y-mu, d0z=v0.z-mu, d0w=v0.w-mu;
    float d1x=v1.x-mu, d1y=v1.y-mu, d1z=v1.z-mu, d1w=v1.w-mu;
    float q = d0x*d0x+d0y*d0y+d0z*d0z+d0w*d0w + d1x*d1x+d1y*d1y+d1z*d1z+d1w*d1w;
    #pragma unroll
    for (int o = 16; o; o >>= 1) q += __shfl_xor_sync(0xffffffffu, q, o);
    float inv = rsqrtf(q * (1.f/256.f) + 1e-5f);

    const float4* gp = (const float4*)gamma;
    const float4* bp = (const float4*)beta;
    float4 g0 = gp[lane], g1v = gp[lane+32];
    float4 b0 = bp[lane], b1v = bp[lane+32];

    __half2 h0 = __floats2half2_rn(d0x*inv*g0.x + b0.x, d0y*inv*g0.y + b0.y);
    __half2 h1 = __floats2half2_rn(d0z*inv*g0.z + b0.z, d0w*inv*g0.w + b0.w);
    __half2 h2 = __floats2half2_rn(d1x*inv*g1v.x + b1v.x, d1y*inv*g1v.y + b1v.y);
    __half2 h3 = __floats2half2_rn(d1z*inv*g1v.z + b1v.z, d1w*inv*g1v.w + b1v.w);

    __half* outp = &g_xnh[(size_t)r*CCH];
    ((uint2*)outp)[lane]      = make_uint2(*(uint32_t*)&h0, *(uint32_t*)&h1);
    ((uint2*)outp)[lane + 32] = make_uint2(*(uint32_t*)&h2, *(uint32_t*)&h3);
}

// ---------------- Windowed attention: fp16 q/k/v smem, half2 tile loads ------
#define QR 52                      // 49 rounded up to 4
#define HS 34                      // half row stride: even (4B-aligned half2),
                                   // 4-row tile stride 68 words%32=4 -> <=2-way
__global__ void attn_kernel() {
    __shared__ __half qs[QR][HS];
    __shared__ __half ks[QR][HS];
    __shared__ __half vs[NWT][HS];
    __shared__ float  at[QR][50];

    int blk  = blockIdx.x;
    int head = blk & 7;
    int Bidx = blk >> 3;
    size_t base = (size_t)blk * NWT * HD;
    int tid = threadIdx.x;
    int lane = tid & 31, wid = tid >> 5;

    const __half2* qp = (const __half2*)&g_q[base];
    const __half2* kp = (const __half2*)&g_k[base];
    const __half2* vp = (const __half2*)&g_v[base];
    for (int i = tid; i < NWT*16; i += 256) {
        int r = i >> 4, d2 = (i & 15) * 2;
        *(__half2*)&qs[r][d2] = qp[i];
        *(__half2*)&ks[r][d2] = kp[i];
        *(__half2*)&vs[r][d2] = vp[i];
    }
    // zero the 3 padding rows (49..51)
    if (tid < 96) {
        int r = 49 + tid/32, d = tid & 31;
        qs[r][d] = __ushort_as_half(0); ks[r][d] = __ushort_as_half(0);
    }
    __syncthreads();

    // ---- QK^T: 13x13 tiles of 4x4, half2 loads ------------------------------
    if (tid < 169) {
        int rg = tid / 13, mg = tid % 13;
        int r0 = rg*4, m0 = mg*4;
        float acc[4][4];
        #pragma unroll
        for (int i = 0; i < 4; i++)
            #pragma unroll
            for (int j = 0; j < 4; j++) acc[i][j] = 0.f;
        #pragma unroll 4
        for (int d = 0; d < HD; d += 2) {
            float2 qv[4], kv[4];
            #pragma unroll
            for (int i = 0; i < 4; i++) qv[i] = __half22float2(*(const __half2*)&qs[r0+i][d]);
            #pragma unroll
            for (int j = 0; j < 4; j++) kv[j] = __half22float2(*(const __half2*)&ks[m0+j][d]);
            #pragma unroll
            for (int i = 0; i < 4; i++)
                #pragma unroll
                for (int j = 0; j < 4; j++)
                    acc[i][j] += qv[i].x*kv[j].x + qv[i].y*kv[j].y;
        }
        #pragma unroll
        for (int i = 0; i < 4; i++) {
            int r = r0 + i;
            if (r < NWT) {
                int rq = r/GW, rr = r%GW;
                #pragma unroll
                for (int j = 0; j < 4; j++) {
                    int m = m0 + j;
                    if (m < NWT) {
                        int dh = rq - m/GW + 6;
                        int dw = rr - m%GW + 6;
                        at[r][m] = acc[i][j] + g_pos[(dh*13 + dw)*NHH + head];
                    }
                }
            }
        }
    }
    __syncthreads();

    // ---- softmax: warp-parallel over rows -----------------------------------
    for (int r = wid; r < NWT; r += 8) {
        float v0 = at[r][lane];
        float v1 = (lane < NWT - 32) ? at[r][lane + 32] : -1e30f;
        float mx = fmaxf(v0, v1);
        #pragma unroll
        for (int o = 16; o; o >>= 1) mx = fmaxf(mx, __shfl_xor_sync(0xffffffffu, mx, o));
        float e0 = __expf(v0 - mx);
        float e1 = (lane < NWT - 32) ? __expf(v1 - mx) : 0.f;
        float s = e0 + e1;
        #pragma unroll
        for (int o = 16; o; o >>= 1) s += __shfl_xor_sync(0xffffffffu, s, o);
        float inv = 1.f / s;
        at[r][lane] = e0 * inv;
        if (lane < NWT - 32) at[r][lane + 32] = e1 * inv;
    }
    // zero padding rows of at so PV on rows 49..51 reads finite values
    if (tid < 3*NWT) {
        int r = 49 + tid/NWT, m = tid % NWT;
        at[r][m] = 0.f;
    }
    __syncthreads();

    // ---- P*V: 13x8 tiles of 4 rows x 4 cols, half2 v loads ------------------
    if (tid < 104) {
        int rg = tid >> 3, dg = tid & 7;
        int r0 = rg*4, d0 = dg*4;
        float acc[4][4];
        #pragma unroll
        for (int i = 0; i < 4; i++)
            #pragma unroll
            for (int j = 0; j < 4; j++) acc[i][j] = 0.f;
        #pragma unroll 7
        for (int m = 0; m < NWT; m++) {
            float av[4];
            #pragma unroll
            for (int i = 0; i < 4; i++) av[i] = at[r0+i][m];
            float2 vv0 = __half22float2(*(const __half2*)&vs[m][d0]);
            float2 vv1 = __half22float2(*(const __half2*)&vs[m][d0+2]);
            float vv[4] = {vv0.x, vv0.y, vv1.x, vv1.y};
            #pragma unroll
            for (int i = 0; i < 4; i++)
                #pragma unroll
                for (int j = 0; j < 4; j++) acc[i][j] += av[i]*vv[j];
        }
        #pragma unroll
        for (int i = 0; i < 4; i++) {
            int r = r0 + i;
            if (r < NWT) {
                size_t o = ((size_t)Bidx*NWT + r)*CCH + head*HD + d0;
                *(__half2*)&g_awinh[o]     = __floats2half2_rn(acc[i][0], acc[i][1]);
                *(__half2*)&g_awinh[o + 2] = __floats2half2_rn(acc[i][2], acc[i][3]);
            }
        }
    }
}

// ---------------- launch ----------------------------------------------------
extern "C" void kernel_launch(void* const* d_in, const int* in_sizes, int n_in,
                              void* d_out, int out_size) {
    const float* x        = (const float*)d_in[0];
    const float* norm1_g  = (const float*)d_in[1];
    const float* norm1_b  = (const float*)d_in[2];
    const float* qkv_w    = (const float*)d_in[3];
    const float* qkv_b    = (const float*)d_in[4];
    const float* proj_w   = (const float*)d_in[5];
    const float* proj_b   = (const float*)d_in[6];
    const float* pos_pw   = (const float*)d_in[7];
    const float* pos_pb   = (const float*)d_in[8];
    const float* p1g      = (const float*)d_in[9];
    const float* p1b      = (const float*)d_in[10];
    const float* p1w      = (const float*)d_in[11];
    const float* p1wb     = (const float*)d_in[12];
    const float* p2g      = (const float*)d_in[13];
    const float* p2b      = (const float*)d_in[14];
    const float* p2w      = (const float*)d_in[15];
    const float* p2wb     = (const float*)d_in[16];
    const float* p3g      = (const float*)d_in[17];
    const float* p3b      = (const float*)d_in[18];
    const float* p3w      = (const float*)d_in[19];
    const float* p3wb     = (const float*)d_in[20];
    const float* norm2_g  = (const float*)d_in[21];
    const float* norm2_b  = (const float*)d_in[22];
    const float* fc1_w    = (const float*)d_in[23];
    const float* fc1_b    = (const float*)d_in[24];
    const float* fc2_w    = (const float*)d_in[25];
    const float* fc2_b    = (const float*)d_in[26];
    float* out = (float*)d_out;

    cudaFuncSetAttribute(gemm_mma<0,768,256>,  cudaFuncAttributeMaxDynamicSharedMemorySize, SMEM_TOT);
    cudaFuncSetAttribute(gemm_mma<1,256,256>,  cudaFuncAttributeMaxDynamicSharedMemorySize, SMEM_TOT);
    cudaFuncSetAttribute(gemm_mma<2,1024,256>, cudaFuncAttributeMaxDynamicSharedMemorySize, SMEM_TOT);
    cudaFuncSetAttribute(gemm_mma<3,256,1024>, cudaFuncAttributeMaxDynamicSharedMemorySize, SMEM_TOT);

    // launch order: prep(0), ln1(1), qkv(2), attn(3) -> ncu profiles attn
    prep_kernel<<<3073, 256>>>(qkv_w, proj_w, fc1_w, fc2_w,
                               pos_pw, pos_pb, p1g, p1b, p1w, p1wb,
                               p2g, p2b, p2w, p2wb, p3g, p3b, p3w, p3wb);
    ln_kernel<<<ROWS/8, 256>>>(x, norm1_g, norm1_b, 0);
    gemm_mma<0,768,256><<<dim3(6, ROWS/128), 256, SMEM_TOT>>>(WOFF_QKV, qkv_b, nullptr, nullptr);
    attn_kernel<<<BWIN*NHH, 256>>>();
    gemm_mma<1,256,256><<<dim3(2, ROWS/128), 256, SMEM_TOT>>>(WOFF_PROJ, proj_b, x, nullptr);
    ln_kernel<<<ROWS/8, 256>>>(nullptr, norm2_g, norm2_b, 1);
    gemm_mma<2,1024,256><<<dim3(8, ROWS/128), 256, SMEM_TOT>>>(WOFF_FC1, fc1_b, nullptr, nullptr);
    gemm_mma<3,256,1024><<<dim3(2, ROWS/128), 256, SMEM_TOT>>>(WOFF_FC2, fc2_b, nullptr, out);
}

// round 16
// speedup vs baseline: 1.9455x; 1.2052x over previous
#include <cuda_runtime.h>
#include <cuda_fp16.h>
#include <math.h>
#include <stdint.h>

#define BB    32
#define HRESD 56
#define WRESD 56
#define CCH   256
#define LLEN  (HRESD*WRESD)          // 3136
#define ROWS  (BB*LLEN)              // 100352
#define NHH   8
#define HD    32
#define GW    7
#define NWT   49
#define NWIN  64
#define BWIN  (BB*NWIN)              // 2048
#define HID   1024
#define QSCALE 0.17677669529663687f

// ---------------- scratch ---------------------------------------------------
__device__ __align__(128) __half g_xnh [(size_t)ROWS*CCH];   // LN out (fp16)
__device__ __align__(128) __half g_awinh[(size_t)ROWS*CCH];  // attn out (fp16)
__device__ __align__(128) __half g_hidh[(size_t)ROWS*HID];   // gelu out (fp16)
__device__ __align__(128) __half g_wth [786432];             // weights fp16, transposed
__device__ __align__(128) __half g_q   [(size_t)BWIN*NHH*NWT*HD];
__device__ __align__(128) __half g_k   [(size_t)BWIN*NHH*NWT*HD];
__device__ __align__(128) __half g_v   [(size_t)BWIN*NHH*NWT*HD];
__device__ float g_x1  [(size_t)ROWS*CCH];
__device__ float g_pos [169*NHH];

#define WOFF_QKV  0
#define WOFF_PROJ 196608
#define WOFF_FC1  262144
#define WOFF_FC2  524288

// ---------------- helpers ----------------------------------------------------
__device__ __forceinline__ uint32_t smem_u32(const void* p) {
    uint32_t a;
    asm("{ .reg .u64 t; cvta.to.shared.u64 t, %1; cvt.u32.u64 %0, t; }" : "=r"(a) : "l"(p));
    return a;
}
__device__ __forceinline__ void ldsm4(uint32_t* r, uint32_t addr) {
    asm volatile("ldmatrix.sync.aligned.m8n8.x4.shared.b16 {%0,%1,%2,%3}, [%4];"
                 : "=r"(r[0]), "=r"(r[1]), "=r"(r[2]), "=r"(r[3]) : "r"(addr));
}
__device__ __forceinline__ void mma16816(float* c, const uint32_t* a, const uint32_t* b) {
    asm volatile("mma.sync.aligned.m16n8k16.row.col.f32.f16.f16.f32 "
                 "{%0,%1,%2,%3}, {%4,%5,%6,%7}, {%8,%9}, {%0,%1,%2,%3};"
                 : "+f"(c[0]), "+f"(c[1]), "+f"(c[2]), "+f"(c[3])
                 : "r"(a[0]), "r"(a[1]), "r"(a[2]), "r"(a[3]), "r"(b[0]), "r"(b[1]));
}
#define CP16(dst, src) asm volatile("cp.async.cg.shared.global [%0], [%1], 16;" :: "r"(dst), "l"(src))
#define CP_COMMIT()    asm volatile("cp.async.commit_group;")
#define CP_WAIT0()     asm volatile("cp.async.wait_group 0;")
#define CP_WAIT1()     asm volatile("cp.async.wait_group 1;")

#define SSTR    72
#define ARR_B   (128*SSTR*2)           // 18432 B
#define STAGE_B (2*ARR_B)              // Ah + Bh = 36864 B
#define SMEM_TOT (3*STAGE_B)           // 110592 B -> 2 CTAs/SM

// ---------------- 3-stage fp16 GEMM: 128x128 tile, BK=64 (proven) ------------
// EPI: 0=QKV  1=PROJ  2=FC1+GELU  3=FC2+res
template<int EPI, int NC, int KC>
__global__ __launch_bounds__(256, 2) void gemm_mma(size_t woff,
                                                   const float* __restrict__ bias,
                                                   const float* __restrict__ X,
                                                   float* __restrict__ Out) {
    extern __shared__ char smc[];
    uint32_t smb = smem_u32(smc);

    const __half* A_g  = (EPI == 1) ? g_awinh : (EPI == 3 ? g_hidh : g_xnh);
    const __half* Bh_g = g_wth + woff;

    int tid  = threadIdx.x;
    int lane = tid & 31, wid = tid >> 5;
    int warpM = wid & 3, warpN = wid >> 2;        // 4 x 2 warp grid, 32x64 each
    int rbase = blockIdx.y * 128;
    int cbase = blockIdx.x * 128;

    float acc[2][8][4];
    #pragma unroll
    for (int mi = 0; mi < 2; mi++)
        #pragma unroll
        for (int nj = 0; nj < 8; nj++)
            #pragma unroll
            for (int e = 0; e < 4; e++) acc[mi][nj][e] = 0.f;

    const int arow = tid >> 3;
    const int kc8  = (tid & 7) * 8;

    auto issueTile = [&](int t) {
        int kt = t * 64;
        uint32_t sb = smb + (uint32_t)((t % 3) * STAGE_B);
        #pragma unroll
        for (int u = 0; u < 4; u++) {
            int row = u*32 + arow;
            CP16(sb + (uint32_t)((row*SSTR + kc8)*2),
                 A_g + (size_t)(rbase + row)*KC + kt + kc8);
        }
        #pragma unroll
        for (int u = 0; u < 4; u++) {
            int row = u*32 + arow;
            CP16(sb + (uint32_t)(ARR_B + (row*SSTR + kc8)*2),
                 Bh_g + (size_t)(cbase + row)*KC + kt + kc8);
        }
    };

    const int T = KC / 64;
    issueTile(0); CP_COMMIT();
    issueTile(1); CP_COMMIT();

    for (int t = 0; t < T; t++) {
        if (t + 1 < T) { CP_WAIT1(); } else { CP_WAIT0(); }
        __syncthreads();
        if (t + 2 < T) { issueTile(t + 2); CP_COMMIT(); }

        uint32_t ahb = smb + (uint32_t)((t % 3) * STAGE_B);
        uint32_t bhb = ahb + ARR_B;

        #pragma unroll
        for (int k0 = 0; k0 < 64; k0 += 16) {
            uint32_t a_h[2][4];
            #pragma unroll
            for (int mi = 0; mi < 2; mi++) {
                int row = warpM*32 + mi*16 + (lane & 15);
                int col = k0 + ((lane & 16) >> 1);
                ldsm4(a_h[mi], ahb + (uint32_t)(row*SSTR + col)*2);
            }
            #pragma unroll
            for (int j = 0; j < 4; j++) {
                int row = warpN*64 + j*16 + (lane & 7) + ((lane & 16) >> 1);
                int col = k0 + (lane & 8);
                uint32_t r[4];
                ldsm4(r, bhb + (uint32_t)(row*SSTR + col)*2);
                mma16816(acc[0][j*2],   a_h[0], r);
                mma16816(acc[0][j*2+1], a_h[0], r+2);
                mma16816(acc[1][j*2],   a_h[1], r);
                mma16816(acc[1][j*2+1], a_h[1], r+2);
            }
        }
    }

    // ---- epilogue -----------------------------------------------------------
    #pragma unroll
    for (int mi = 0; mi < 2; mi++)
        #pragma unroll
        for (int eh = 0; eh < 2; eh++) {
            int row = rbase + warpM*32 + mi*16 + (lane >> 2) + eh*8;

            if (EPI == 0) {
                int b  = row / LLEN, l = row % LLEN;
                int hh = l / WRESD, wc = l % WRESD;
                int wh = hh / GW, ii = hh % GW;
                int wn = wc / GW, jj = wc % GW;
                int Bidx = b*NWIN + wh*8 + wn;
                int n = ii*GW + jj;
                size_t rb = (size_t)Bidx*(NHH*NWT*HD) + (size_t)n*HD;
                #pragma unroll
                for (int nj = 0; nj < 8; nj++) {
                    int c = cbase + warpN*64 + nj*8 + (lane & 3)*2;
                    float2 bv = *(const float2*)&bias[c];
                    float v0 = acc[mi][nj][eh*2+0] + bv.x;
                    float v1 = acc[mi][nj][eh*2+1] + bv.y;
                    int sect = c >> 8;
                    int head = (c >> 5) & 7;
                    int d    = c & 31;
                    size_t idx = rb + (size_t)head*(NWT*HD) + d;
                    if (sect == 0)
                        *(__half2*)&g_q[idx] = __floats2half2_rn(v0*QSCALE, v1*QSCALE);
                    else if (sect == 1)
                        *(__half2*)&g_k[idx] = __floats2half2_rn(v0, v1);
                    else
                        *(__half2*)&g_v[idx] = __floats2half2_rn(v0, v1);
                }
            } else if (EPI == 1) {
                int Bidx = row / NWT, n = row % NWT;
                int b  = Bidx / NWIN, wi = Bidx % NWIN;
                int wh = wi / 8, wn = wi % 8;
                int ii = n / GW, jj = n % GW;
                int l  = (wh*GW + ii)*WRESD + wn*GW + jj;
                size_t rowoff = ((size_t)b*LLEN + l)*CCH;
                #pragma unroll
                for (int nj = 0; nj < 8; nj++) {
                    int c = cbase + warpN*64 + nj*8 + (lane & 3)*2;
                    float2 bv = *(const float2*)&bias[c];
                    float2 xv = *(const float2*)&X[rowoff + c];
                    *(float2*)&g_x1[rowoff + c] =
                        make_float2(xv.x + acc[mi][nj][eh*2+0] + bv.x,
                                    xv.y + acc[mi][nj][eh*2+1] + bv.y);
                }
            } else if (EPI == 2) {
                size_t rowoff = (size_t)row*HID;
                #pragma unroll
                for (int nj = 0; nj < 8; nj++) {
                    int c = cbase + warpN*64 + nj*8 + (lane & 3)*2;
                    float2 bv = *(const float2*)&bias[c];
                    float v0 = acc[mi][nj][eh*2+0] + bv.x;
                    float v1 = acc[mi][nj][eh*2+1] + bv.y;
                    float g0 = 0.5f*v0*(1.f + erff(v0*0.70710678118654752f));
                    float g1 = 0.5f*v1*(1.f + erff(v1*0.70710678118654752f));
                    *(__half2*)&g_hidh[rowoff + c] = __floats2half2_rn(g0, g1);
                }
            } else {
                size_t rowoff = (size_t)row*CCH;
                #pragma unroll
                for (int nj = 0; nj < 8; nj++) {
                    int c = cbase + warpN*64 + nj*8 + (lane & 3)*2;
                    float2 bv = *(const float2*)&bias[c];
                    float2 xv = *(const float2*)&g_x1[rowoff + c];
                    *(float2*)&Out[rowoff + c] =
                        make_float2(xv.x + acc[mi][nj][eh*2+0] + bv.x,
                                    xv.y + acc[mi][nj][eh*2+1] + bv.y);
                }
            }
        }
}

// ---------------- DynamicPosBias MLP (device fn) -----------------------------
__device__ __forceinline__ void pos_stage(float* t, const float* g, const float* b,
                                          const float* w, const float* wb, int outn) {
    float mu = 0.f;
    #pragma unroll
    for (int p = 0; p < 16; p++) mu += t[p];
    mu *= (1.f/16.f);
    float var = 0.f;
    #pragma unroll
    for (int p = 0; p < 16; p++) { float d = t[p]-mu; var += d*d; }
    var *= (1.f/16.f);
    float inv = rsqrtf(var + 1e-5f);
    float u[16];
    #pragma unroll
    for (int p = 0; p < 16; p++) {
        float z = (t[p]-mu)*inv*g[p] + b[p];
        u[p] = fmaxf(z, 0.f);
    }
    for (int q = 0; q < outn; q++) {
        float s = wb[q];
        #pragma unroll
        for (int p = 0; p < 16; p++) s += u[p]*w[p*outn + q];
        t[q] = s;
    }
}

// ---------------- fused prep: 4 weight transposes + pos MLP ------------------
__global__ void prep_kernel(const float* __restrict__ w_qkv,
                            const float* __restrict__ w_proj,
                            const float* __restrict__ w_fc1,
                            const float* __restrict__ w_fc2,
                            const float* pw, const float* pb,
                            const float* g1, const float* b1, const float* w1, const float* wb1,
                            const float* g2, const float* b2, const float* w2, const float* wb2,
                            const float* g3, const float* b3, const float* w3, const float* wb3) {
    if (blockIdx.x == 3072) {
        int i = threadIdx.x;
        if (i >= 169) return;
        float bh = (float)(i/13 - 6);
        float bw = (float)(i%13 - 6);
        float t[16];
        #pragma unroll
        for (int p = 0; p < 16; p++) t[p] = bh*pw[p] + bw*pw[16+p] + pb[p];
        pos_stage(t, g1, b1, w1, wb1, 16);
        pos_stage(t, g2, b2, w2, wb2, 16);
        pos_stage(t, g3, b3, w3, wb3, NHH);
        #pragma unroll
        for (int h = 0; h < NHH; h++) g_pos[i*NHH + h] = t[h];
        return;
    }
    int idx = blockIdx.x*256 + threadIdx.x;   // == destination offset in g_wth
    const float* w; int K, N, off;
    if (idx < WOFF_PROJ)      { w = w_qkv;  K = 256;  N = 768;  off = WOFF_QKV;  }
    else if (idx < WOFF_FC1)  { w = w_proj; K = 256;  N = 256;  off = WOFF_PROJ; }
    else if (idx < WOFF_FC2)  { w = w_fc1;  K = 256;  N = 1024; off = WOFF_FC1;  }
    else                      { w = w_fc2;  K = 1024; N = 256;  off = WOFF_FC2;  }
    int local = idx - off;
    int n = local / K, k = local - n*K;
    g_wth[idx] = __float2half_rn(w[(size_t)k*N + n]);
}

// ---------------- LayerNorm: warp per row, 8 rows/block ----------------------
__global__ void ln_kernel(const float* __restrict__ xin,
                          const float* __restrict__ gamma,
                          const float* __restrict__ beta, int src) {
    int warp = threadIdx.x >> 5, lane = threadIdx.x & 31;
    int r = blockIdx.x*8 + warp;
    const float* in = src ? g_x1 : xin;
    const float4* p = (const float4*)&in[(size_t)r*CCH];
    float4 v0 = p[lane];
    float4 v1 = p[lane + 32];

    float s = v0.x+v0.y+v0.z+v0.w + v1.x+v1.y+v1.z+v1.w;
    #pragma unroll
    for (int o = 16; o; o >>= 1) s += __shfl_xor_sync(0xffffffffu, s, o);
    float mu = s * (1.f/256.f);

    float d0x=v0.x-mu, d0y=v0.y-mu, d0z=v0.z-mu, d0w=v0.w-mu;
    float d1x=v1.x-mu, d1y=v1.y-mu, d1z=v1.z-mu, d1w=v1.w-mu;
    float q = d0x*d0x+d0y*d0y+d0z*d0z+d0w*d0w + d1x*d1x+d1y*d1y+d1z*d1z+d1w*d1w;
    #pragma unroll
    for (int o = 16; o; o >>= 1) q += __shfl_xor_sync(0xffffffffu, q, o);
    float inv = rsqrtf(q * (1.f/256.f) + 1e-5f);

    const float4* gp = (const float4*)gamma;
    const float4* bp = (const float4*)beta;
    float4 g0 = gp[lane], g1v = gp[lane+32];
    float4 b0 = bp[lane], b1v = bp[lane+32];

    __half2 h0 = __floats2half2_rn(d0x*inv*g0.x + b0.x, d0y*inv*g0.y + b0.y);
    __half2 h1 = __floats2half2_rn(d0z*inv*g0.z + b0.z, d0w*inv*g0.w + b0.w);
    __half2 h2 = __floats2half2_rn(d1x*inv*g1v.x + b1v.x, d1y*inv*g1v.y + b1v.y);
    __half2 h3 = __floats2half2_rn(d1z*inv*g1v.z + b1v.z, d1w*inv*g1v.w + b1v.w);

    __half* outp = &g_xnh[(size_t)r*CCH];
    ((uint2*)outp)[lane]      = make_uint2(*(uint32_t*)&h0, *(uint32_t*)&h1);
    ((uint2*)outp)[lane + 32] = make_uint2(*(uint32_t*)&h2, *(uint32_t*)&h3);
}

// ---------------- Windowed attention: mma.sync flash-style -------------------
// 4 warps/block; each warp = one (window, head). grid = BWIN*2.
#define AQ_S  40                      // q/k smem row stride (halves); 80B = 16B-mult
#define AV_S  72                      // vt row stride; 144B = 16B-mult
#define AH_REG ((64*AQ_S + 64*AQ_S + 32*AV_S)*2)   // 14848 B per head
#define ATTN_SM (4*AH_REG + 4*169*4)               // 62096 B

__global__ __launch_bounds__(128) void attn_kernel() {
    extern __shared__ char asmem[];
    int tid = threadIdx.x, lane = tid & 31, w = tid >> 5;
    int win  = blockIdx.x >> 1;
    int head = (blockIdx.x & 1)*4 + w;

    __half* qs = (__half*)(asmem + (size_t)w*AH_REG);
    __half* ks = qs + 64*AQ_S;
    __half* vt = ks + 64*AQ_S;
    float*  pos_s = (float*)(asmem + 4*AH_REG) + w*169;

    size_t base = ((size_t)win*NHH + head)*(NWT*HD);
    const __half2* qp = (const __half2*)&g_q[base];
    const __half2* kp = (const __half2*)&g_k[base];
    const __half2* vp = (const __half2*)&g_v[base];

    for (int i = lane; i < NWT*16; i += 32) {
        int r = i >> 4, c2 = (i & 15)*2;
        *(__half2*)&qs[r*AQ_S + c2] = qp[i];
        *(__half2*)&ks[r*AQ_S + c2] = kp[i];
        __half2 v = vp[i];
        vt[(size_t)c2*AV_S + r]     = __low2half(v);
        vt[(size_t)(c2+1)*AV_S + r] = __high2half(v);
    }
    __half2 z2; *(uint32_t*)&z2 = 0;
    for (int i = lane; i < 15*16; i += 32) {
        int r = 49 + (i >> 4), c2 = (i & 15)*2;
        *(__half2*)&qs[r*AQ_S + c2] = z2;
        *(__half2*)&ks[r*AQ_S + c2] = z2;
    }
    for (int i = lane; i < 32*16; i += 32) {
        int d = i >> 4, kk = 48 + (i & 15);
        if (kk >= NWT) vt[d*AV_S + kk] = __ushort_as_half(0);
    }
    for (int i = lane; i < 169; i += 32) pos_s[i] = g_pos[i*NHH + head];
    __syncwarp();

    uint32_t qb = smem_u32(qs), kb = smem_u32(ks), vb = smem_u32(vt);
    const uint32_t aoff = (uint32_t)((lane & 15)*AQ_S + ((lane & 16) >> 1)) * 2;
    const uint32_t koff = (uint32_t)(((lane & 7) + ((lane & 16) >> 1))*AQ_S + (lane & 8)) * 2;
    const uint32_t voff = (uint32_t)(((lane & 7) + ((lane & 16) >> 1))*AV_S + (lane & 8)) * 2;

    #pragma unroll 1
    for (int mt = 0; mt < 4; mt++) {
        int m0 = mt*16;
        uint32_t qa[2][4];
        ldsm4(qa[0], qb + aoff + (uint32_t)(m0*AQ_S)*2);
        ldsm4(qa[1], qb + aoff + (uint32_t)(m0*AQ_S + 16)*2);

        float sc[7][4];
        #pragma unroll
        for (int t = 0; t < 7; t++)
            #pragma unroll
            for (int e = 0; e < 4; e++) sc[t][e] = 0.f;

        #pragma unroll
        for (int kt2 = 0; kt2 < 2; kt2++)
            #pragma unroll
            for (int jn = 0; jn < 4; jn++) {
                uint32_t r[4];
                ldsm4(r, kb + koff + (uint32_t)(jn*16*AQ_S + kt2*16)*2);
                mma16816(sc[jn*2], qa[kt2], r);
                if (jn*2 + 1 < 7) mma16816(sc[jn*2+1], qa[kt2], r+2);
            }

        int ra = m0 + (lane >> 2), rb2 = ra + 8;
        bool va = ra < NWT, vbv = rb2 < NWT;
        int raq = ra/GW, rar = ra - raq*GW;
        int rbq = rb2/GW, rbr = rb2 - rbq*GW;
        float mxa = -1e30f, mxb = -1e30f;
        #pragma unroll
        for (int t = 0; t < 7; t++) {
            #pragma unroll
            for (int e = 0; e < 2; e++) {
                int c = t*8 + (lane & 3)*2 + e;
                if (c < NWT) {
                    int cq = c/GW, cr = c - cq*GW;
                    if (va)  sc[t][e]   += pos_s[(raq-cq+6)*13 + (rar-cr+6)];
                    if (vbv) sc[t][2+e] += pos_s[(rbq-cq+6)*13 + (rbr-cr+6)];
                } else {
                    sc[t][e] = -1e30f; sc[t][2+e] = -1e30f;
                }
            }
            mxa = fmaxf(mxa, fmaxf(sc[t][0], sc[t][1]));
            mxb = fmaxf(mxb, fmaxf(sc[t][2], sc[t][3]));
        }
        mxa = fmaxf(mxa, __shfl_xor_sync(0xffffffffu, mxa, 1));
        mxa = fmaxf(mxa, __shfl_xor_sync(0xffffffffu, mxa, 2));
        mxb = fmaxf(mxb, __shfl_xor_sync(0xffffffffu, mxb, 1));
        mxb = fmaxf(mxb, __shfl_xor_sync(0xffffffffu, mxb, 2));

        float sa = 0.f, sb = 0.f;
        #pragma unroll
        for (int t = 0; t < 7; t++) {
            sc[t][0] = __expf(sc[t][0] - mxa);
            sc[t][1] = __expf(sc[t][1] - mxa);
            sc[t][2] = __expf(sc[t][2] - mxb);
            sc[t][3] = __expf(sc[t][3] - mxb);
            sa += sc[t][0] + sc[t][1];
            sb += sc[t][2] + sc[t][3];
        }
        sa += __shfl_xor_sync(0xffffffffu, sa, 1);
        sa += __shfl_xor_sync(0xffffffffu, sa, 2);
        sb += __shfl_xor_sync(0xffffffffu, sb, 1);
        sb += __shfl_xor_sync(0xffffffffu, sb, 2);
        float ia = 1.f/sa, ib = 1.f/sb;

        // pack probs directly into PV A-fragments (C layout == A layout)
        uint32_t pa[4][4];
        #pragma unroll
        for (int kt = 0; kt < 4; kt++) {
            int t0 = 2*kt, t1 = 2*kt + 1;
            __half2 h;
            h = __floats2half2_rn(sc[t0][0]*ia, sc[t0][1]*ia); pa[kt][0] = *(uint32_t*)&h;
            h = __floats2half2_rn(sc[t0][2]*ib, sc[t0][3]*ib); pa[kt][1] = *(uint32_t*)&h;
            if (t1 < 7) {
                h = __floats2half2_rn(sc[t1][0]*ia, sc[t1][1]*ia); pa[kt][2] = *(uint32_t*)&h;
                h = __floats2half2_rn(sc[t1][2]*ib, sc[t1][3]*ib); pa[kt][3] = *(uint32_t*)&h;
            } else { pa[kt][2] = 0; pa[kt][3] = 0; }
        }

        float ov[4][4];
        #pragma unroll
        for (int dt = 0; dt < 4; dt++)
            #pragma unroll
            for (int e = 0; e < 4; e++) ov[dt][e] = 0.f;
        #pragma unroll
        for (int kt = 0; kt < 4; kt++) {
            uint32_t v0[4], v1[4];
            ldsm4(v0, vb + voff + (uint32_t)(kt*16)*2);
            ldsm4(v1, vb + voff + (uint32_t)(16*AV_S + kt*16)*2);
            mma16816(ov[0], pa[kt], v0);
            mma16816(ov[1], pa[kt], v0+2);
            mma16816(ov[2], pa[kt], v1);
            mma16816(ov[3], pa[kt], v1+2);
        }

        #pragma unroll
        for (int dt = 0; dt < 4; dt++) {
            int c = dt*8 + (lane & 3)*2;
            if (va) {
                size_t o = ((size_t)win*NWT + ra)*CCH + head*HD + c;
                *(__half2*)&g_awinh[o] = __floats2half2_rn(ov[dt][0], ov[dt][1]);
            }
            if (vbv) {
                size_t o = ((size_t)win*NWT + rb2)*CCH + head*HD + c;
                *(__half2*)&g_awinh[o] = __floats2half2_rn(ov[dt][2], ov[dt][3]);
            }
        }
    }
}

// ---------------- launch ----------------------------------------------------
extern "C" void kernel_launch(void* const* d_in, const int* in_sizes, int n_in,
                              void* d_out, int out_size) {
    const float* x        = (const float*)d_in[0];
    const float* norm1_g  = (const float*)d_in[1];
    const float* norm1_b  = (const float*)d_in[2];
    const float* qkv_w    = (const float*)d_in[3];
    const float* qkv_b    = (const float*)d_in[4];
    const float* proj_w   = (const float*)d_in[5];
    const float* proj_b   = (const float*)d_in[6];
    const float* pos_pw   = (const float*)d_in[7];
    const float* pos_pb   = (const float*)d_in[8];
    const float* p1g      = (const float*)d_in[9];
    const float* p1b      = (const float*)d_in[10];
    const float* p1w      = (const float*)d_in[11];
    const float* p1wb     = (const float*)d_in[12];
    const float* p2g      = (const float*)d_in[13];
    const float* p2b      = (const float*)d_in[14];
    const float* p2w      = (const float*)d_in[15];
    const float* p2wb     = (const float*)d_in[16];
    const float* p3g      = (const float*)d_in[17];
    const float* p3b      = (const float*)d_in[18];
    const float* p3w      = (const float*)d_in[19];
    const float* p3wb     = (const float*)d_in[20];
    const float* norm2_g  = (const float*)d_in[21];
    const float* norm2_b  = (const float*)d_in[22];
    const float* fc1_w    = (const float*)d_in[23];
    const float* fc1_b    = (const float*)d_in[24];
    const float* fc2_w    = (const float*)d_in[25];
    const float* fc2_b    = (const float*)d_in[26];
    float* out = (float*)d_out;

    cudaFuncSetAttribute(gemm_mma<0,768,256>,  cudaFuncAttributeMaxDynamicSharedMemorySize, SMEM_TOT);
    cudaFuncSetAttribute(gemm_mma<1,256,256>,  cudaFuncAttributeMaxDynamicSharedMemorySize, SMEM_TOT);
    cudaFuncSetAttribute(gemm_mma<2,1024,256>, cudaFuncAttributeMaxDynamicSharedMemorySize, SMEM_TOT);
    cudaFuncSetAttribute(gemm_mma<3,256,1024>, cudaFuncAttributeMaxDynamicSharedMemorySize, SMEM_TOT);
    cudaFuncSetAttribute(attn_kernel, cudaFuncAttributeMaxDynamicSharedMemorySize, ATTN_SM);

    // launch order: prep(0), ln1(1), qkv(2), attn(3) -> ncu profiles attn
    prep_kernel<<<3073, 256>>>(qkv_w, proj_w, fc1_w, fc2_w,
                               pos_pw, pos_pb, p1g, p1b, p1w, p1wb,
                               p2g, p2b, p2w, p2wb, p3g, p3b, p3w, p3wb);
    ln_kernel<<<ROWS/8, 256>>>(x, norm1_g, norm1_b, 0);
    gemm_mma<0,768,256><<<dim3(6, ROWS/128), 256, SMEM_TOT>>>(WOFF_QKV, qkv_b, nullptr, nullptr);
    attn_kernel<<<BWIN*2, 128, ATTN_SM>>>();
    gemm_mma<1,256,256><<<dim3(2, ROWS/128), 256, SMEM_TOT>>>(WOFF_PROJ, proj_b, x, nullptr);
    ln_kernel<<<ROWS/8, 256>>>(nullptr, norm2_g, norm2_b, 1);
    gemm_mma<2,1024,256><<<dim3(8, ROWS/128), 256, SMEM_TOT>>>(WOFF_FC1, fc1_b, nullptr, nullptr);
    gemm_mma<3,256,1024><<<dim3(2, ROWS/128), 256, SMEM_TOT>>>(WOFF_FC2, fc2_b, nullptr, out);
}

// round 17
// speedup vs baseline: 1.9939x; 1.0248x over previous
#include <cuda_runtime.h>
#include <cuda_fp16.h>
#include <math.h>
#include <stdint.h>

#define BB    32
#define HRESD 56
#define WRESD 56
#define CCH   256
#define LLEN  (HRESD*WRESD)          // 3136
#define ROWS  (BB*LLEN)              // 100352
#define NHH   8
#define HD    32
#define GW    7
#define NWT   49
#define NWIN  64
#define BWIN  (BB*NWIN)              // 2048
#define HID   1024
#define QSCALE 0.17677669529663687f

// ---------------- scratch ---------------------------------------------------
__device__ __align__(128) __half g_xnh [(size_t)ROWS*CCH];   // LN out (fp16)
__device__ __align__(128) __half g_awinh[(size_t)ROWS*CCH];  // attn out (fp16)
__device__ __align__(128) __half g_hidh[(size_t)ROWS*HID];   // gelu out (fp16)
__device__ __align__(128) __half g_wth [786432];             // weights fp16, transposed
__device__ __align__(128) __half g_q   [(size_t)BWIN*NHH*NWT*HD];
__device__ __align__(128) __half g_k   [(size_t)BWIN*NHH*NWT*HD];
__device__ __align__(128) __half g_v   [(size_t)BWIN*NHH*NWT*HD];
__device__ float g_x1  [(size_t)ROWS*CCH];
__device__ float g_pos [169*NHH];

#define WOFF_QKV  0
#define WOFF_PROJ 196608
#define WOFF_FC1  262144
#define WOFF_FC2  524288

// ---------------- helpers ----------------------------------------------------
__device__ __forceinline__ uint32_t smem_u32(const void* p) {
    uint32_t a;
    asm("{ .reg .u64 t; cvta.to.shared.u64 t, %1; cvt.u32.u64 %0, t; }" : "=r"(a) : "l"(p));
    return a;
}
__device__ __forceinline__ void ldsm4(uint32_t* r, uint32_t addr) {
    asm volatile("ldmatrix.sync.aligned.m8n8.x4.shared.b16 {%0,%1,%2,%3}, [%4];"
                 : "=r"(r[0]), "=r"(r[1]), "=r"(r[2]), "=r"(r[3]) : "r"(addr));
}
__device__ __forceinline__ void mma16816(float* c, const uint32_t* a, const uint32_t* b) {
    asm volatile("mma.sync.aligned.m16n8k16.row.col.f32.f16.f16.f32 "
                 "{%0,%1,%2,%3}, {%4,%5,%6,%7}, {%8,%9}, {%0,%1,%2,%3};"
                 : "+f"(c[0]), "+f"(c[1]), "+f"(c[2]), "+f"(c[3])
                 : "r"(a[0]), "r"(a[1]), "r"(a[2]), "r"(a[3]), "r"(b[0]), "r"(b[1]));
}
#define CP16(dst, src) asm volatile("cp.async.cg.shared.global [%0], [%1], 16;" :: "r"(dst), "l"(src))
#define CP_COMMIT()    asm volatile("cp.async.commit_group;")
#define CP_WAIT0()     asm volatile("cp.async.wait_group 0;")
#define CP_WAIT1()     asm volatile("cp.async.wait_group 1;")

#define SSTR    72
#define ARR_B   (128*SSTR*2)           // 18432 B
#define STAGE_B (2*ARR_B)              // Ah + Bh = 36864 B
#define SMEM_TOT (3*STAGE_B)           // 110592 B -> 2 CTAs/SM

// ---------------- 3-stage fp16 GEMM: 128x128 tile, BK=64 (proven) ------------
// EPI: 0=QKV  1=PROJ  2=FC1+GELU  3=FC2+res
template<int EPI, int NC, int KC>
__global__ __launch_bounds__(256, 2) void gemm_mma(size_t woff,
                                                   const float* __restrict__ bias,
                                                   const float* __restrict__ X,
                                                   float* __restrict__ Out) {
    extern __shared__ char smc[];
    uint32_t smb = smem_u32(smc);

    const __half* A_g  = (EPI == 1) ? g_awinh : (EPI == 3 ? g_hidh : g_xnh);
    const __half* Bh_g = g_wth + woff;

    int tid  = threadIdx.x;
    int lane = tid & 31, wid = tid >> 5;
    int warpM = wid & 3, warpN = wid >> 2;        // 4 x 2 warp grid, 32x64 each
    int rbase = blockIdx.y * 128;
    int cbase = blockIdx.x * 128;

    float acc[2][8][4];
    #pragma unroll
    for (int mi = 0; mi < 2; mi++)
        #pragma unroll
        for (int nj = 0; nj < 8; nj++)
            #pragma unroll
            for (int e = 0; e < 4; e++) acc[mi][nj][e] = 0.f;

    const int arow = tid >> 3;
    const int kc8  = (tid & 7) * 8;

    auto issueTile = [&](int t) {
        int kt = t * 64;
        uint32_t sb = smb + (uint32_t)((t % 3) * STAGE_B);
        #pragma unroll
        for (int u = 0; u < 4; u++) {
            int row = u*32 + arow;
            CP16(sb + (uint32_t)((row*SSTR + kc8)*2),
                 A_g + (size_t)(rbase + row)*KC + kt + kc8);
        }
        #pragma unroll
        for (int u = 0; u < 4; u++) {
            int row = u*32 + arow;
            CP16(sb + (uint32_t)(ARR_B + (row*SSTR + kc8)*2),
                 Bh_g + (size_t)(cbase + row)*KC + kt + kc8);
        }
    };

    const int T = KC / 64;
    issueTile(0); CP_COMMIT();
    issueTile(1); CP_COMMIT();

    for (int t = 0; t < T; t++) {
        if (t + 1 < T) { CP_WAIT1(); } else { CP_WAIT0(); }
        __syncthreads();
        if (t + 2 < T) { issueTile(t + 2); CP_COMMIT(); }

        uint32_t ahb = smb + (uint32_t)((t % 3) * STAGE_B);
        uint32_t bhb = ahb + ARR_B;

        #pragma unroll
        for (int k0 = 0; k0 < 64; k0 += 16) {
            uint32_t a_h[2][4];
            #pragma unroll
            for (int mi = 0; mi < 2; mi++) {
                int row = warpM*32 + mi*16 + (lane & 15);
                int col = k0 + ((lane & 16) >> 1);
                ldsm4(a_h[mi], ahb + (uint32_t)(row*SSTR + col)*2);
            }
            #pragma unroll
            for (int j = 0; j < 4; j++) {
                int row = warpN*64 + j*16 + (lane & 7) + ((lane & 16) >> 1);
                int col = k0 + (lane & 8);
                uint32_t r[4];
                ldsm4(r, bhb + (uint32_t)(row*SSTR + col)*2);
                mma16816(acc[0][j*2],   a_h[0], r);
                mma16816(acc[0][j*2+1], a_h[0], r+2);
                mma16816(acc[1][j*2],   a_h[1], r);
                mma16816(acc[1][j*2+1], a_h[1], r+2);
            }
        }
    }

    // ---- epilogue -----------------------------------------------------------
    #pragma unroll
    for (int mi = 0; mi < 2; mi++)
        #pragma unroll
        for (int eh = 0; eh < 2; eh++) {
            int row = rbase + warpM*32 + mi*16 + (lane >> 2) + eh*8;

            if (EPI == 0) {
                int b  = row / LLEN, l = row % LLEN;
                int hh = l / WRESD, wc = l % WRESD;
                int wh = hh / GW, ii = hh % GW;
                int wn = wc / GW, jj = wc % GW;
                int Bidx = b*NWIN + wh*8 + wn;
                int n = ii*GW + jj;
                size_t rb = (size_t)Bidx*(NHH*NWT*HD) + (size_t)n*HD;
                #pragma unroll
                for (int nj = 0; nj < 8; nj++) {
                    int c = cbase + warpN*64 + nj*8 + (lane & 3)*2;
                    float2 bv = *(const float2*)&bias[c];
                    float v0 = acc[mi][nj][eh*2+0] + bv.x;
                    float v1 = acc[mi][nj][eh*2+1] + bv.y;
                    int sect = c >> 8;
                    int head = (c >> 5) & 7;
                    int d    = c & 31;
                    size_t idx = rb + (size_t)head*(NWT*HD) + d;
                    if (sect == 0)
                        *(__half2*)&g_q[idx] = __floats2half2_rn(v0*QSCALE, v1*QSCALE);
                    else if (sect == 1)
                        *(__half2*)&g_k[idx] = __floats2half2_rn(v0, v1);
                    else
                        *(__half2*)&g_v[idx] = __floats2half2_rn(v0, v1);
                }
            } else if (EPI == 1) {
                int Bidx = row / NWT, n = row % NWT;
                int b  = Bidx / NWIN, wi = Bidx % NWIN;
                int wh = wi / 8, wn = wi % 8;
                int ii = n / GW, jj = n % GW;
                int l  = (wh*GW + ii)*WRESD + wn*GW + jj;
                size_t rowoff = ((size_t)b*LLEN + l)*CCH;
                #pragma unroll
                for (int nj = 0; nj < 8; nj++) {
                    int c = cbase + warpN*64 + nj*8 + (lane & 3)*2;
                    float2 bv = *(const float2*)&bias[c];
                    float2 xv = *(const float2*)&X[rowoff + c];
                    *(float2*)&g_x1[rowoff + c] =
                        make_float2(xv.x + acc[mi][nj][eh*2+0] + bv.x,
                                    xv.y + acc[mi][nj][eh*2+1] + bv.y);
                }
            } else if (EPI == 2) {
                size_t rowoff = (size_t)row*HID;
                #pragma unroll
                for (int nj = 0; nj < 8; nj++) {
                    int c = cbase + warpN*64 + nj*8 + (lane & 3)*2;
                    float2 bv = *(const float2*)&bias[c];
                    float v0 = acc[mi][nj][eh*2+0] + bv.x;
                    float v1 = acc[mi][nj][eh*2+1] + bv.y;
                    float g0 = 0.5f*v0*(1.f + erff(v0*0.70710678118654752f));
                    float g1 = 0.5f*v1*(1.f + erff(v1*0.70710678118654752f));
                    *(__half2*)&g_hidh[rowoff + c] = __floats2half2_rn(g0, g1);
                }
            } else {
                size_t rowoff = (size_t)row*CCH;
                #pragma unroll
                for (int nj = 0; nj < 8; nj++) {
                    int c = cbase + warpN*64 + nj*8 + (lane & 3)*2;
                    float2 bv = *(const float2*)&bias[c];
                    float2 xv = *(const float2*)&g_x1[rowoff + c];
                    *(float2*)&Out[rowoff + c] =
                        make_float2(xv.x + acc[mi][nj][eh*2+0] + bv.x,
                                    xv.y + acc[mi][nj][eh*2+1] + bv.y);
                }
            }
        }
}

// ---------------- DynamicPosBias MLP (device fn) -----------------------------
__device__ __forceinline__ void pos_stage(float* t, const float* g, const float* b,
                                          const float* w, const float* wb, int outn) {
    float mu = 0.f;
    #pragma unroll
    for (int p = 0; p < 16; p++) mu += t[p];
    mu *= (1.f/16.f);
    float var = 0.f;
    #pragma unroll
    for (int p = 0; p < 16; p++) { float d = t[p]-mu; var += d*d; }
    var *= (1.f/16.f);
    float inv = rsqrtf(var + 1e-5f);
    float u[16];
    #pragma unroll
    for (int p = 0; p < 16; p++) {
        float z = (t[p]-mu)*inv*g[p] + b[p];
        u[p] = fmaxf(z, 0.f);
    }
    for (int q = 0; q < outn; q++) {
        float s = wb[q];
        #pragma unroll
        for (int p = 0; p < 16; p++) s += u[p]*w[p*outn + q];
        t[q] = s;
    }
}

// ---------------- fused prep: 4 weight transposes + pos MLP ------------------
__global__ void prep_kernel(const float* __restrict__ w_qkv,
                            const float* __restrict__ w_proj,
                            const float* __restrict__ w_fc1,
                            const float* __restrict__ w_fc2,
                            const float* pw, const float* pb,
                            const float* g1, const float* b1, const float* w1, const float* wb1,
                            const float* g2, const float* b2, const float* w2, const float* wb2,
                            const float* g3, const float* b3, const float* w3, const float* wb3) {
    if (blockIdx.x == 3072) {
        int i = threadIdx.x;
        if (i >= 169) return;
        float bh = (float)(i/13 - 6);
        float bw = (float)(i%13 - 6);
        float t[16];
        #pragma unroll
        for (int p = 0; p < 16; p++) t[p] = bh*pw[p] + bw*pw[16+p] + pb[p];
        pos_stage(t, g1, b1, w1, wb1, 16);
        pos_stage(t, g2, b2, w2, wb2, 16);
        pos_stage(t, g3, b3, w3, wb3, NHH);
        #pragma unroll
        for (int h = 0; h < NHH; h++) g_pos[i*NHH + h] = t[h];
        return;
    }
    int idx = blockIdx.x*256 + threadIdx.x;   // == destination offset in g_wth
    const float* w; int K, N, off;
    if (idx < WOFF_PROJ)      { w = w_qkv;  K = 256;  N = 768;  off = WOFF_QKV;  }
    else if (idx < WOFF_FC1)  { w = w_proj; K = 256;  N = 256;  off = WOFF_PROJ; }
    else if (idx < WOFF_FC2)  { w = w_fc1;  K = 256;  N = 1024; off = WOFF_FC1;  }
    else                      { w = w_fc2;  K = 1024; N = 256;  off = WOFF_FC2;  }
    int local = idx - off;
    int n = local / K, k = local - n*K;
    g_wth[idx] = __float2half_rn(w[(size_t)k*N + n]);
}

// ---------------- LayerNorm: warp per row, 8 rows/block ----------------------
__global__ void ln_kernel(const float* __restrict__ xin,
                          const float* __restrict__ gamma,
                          const float* __restrict__ beta, int src) {
    int warp = threadIdx.x >> 5, lane = threadIdx.x & 31;
    int r = blockIdx.x*8 + warp;
    const float* in = src ? g_x1 : xin;
    const float4* p = (const float4*)&in[(size_t)r*CCH];
    float4 v0 = p[lane];
    float4 v1 = p[lane + 32];

    float s = v0.x+v0.y+v0.z+v0.w + v1.x+v1.y+v1.z+v1.w;
    #pragma unroll
    for (int o = 16; o; o >>= 1) s += __shfl_xor_sync(0xffffffffu, s, o);
    float mu = s * (1.f/256.f);

    float d0x=v0.x-mu, d0y=v0.y-mu, d0z=v0.z-mu, d0w=v0.w-mu;
    float d1x=v1.x-mu, d1y=v1.y-mu, d1z=v1.z-mu, d1w=v1.w-mu;
    float q = d0x*d0x+d0y*d0y+d0z*d0z+d0w*d0w + d1x*d1x+d1y*d1y+d1z*d1z+d1w*d1w;
    #pragma unroll
    for (int o = 16; o; o >>= 1) q += __shfl_xor_sync(0xffffffffu, q, o);
    float inv = rsqrtf(q * (1.f/256.f) + 1e-5f);

    const float4* gp = (const float4*)gamma;
    const float4* bp = (const float4*)beta;
    float4 g0 = gp[lane], g1v = gp[lane+32];
    float4 b0 = bp[lane], b1v = bp[lane+32];

    __half2 h0 = __floats2half2_rn(d0x*inv*g0.x + b0.x, d0y*inv*g0.y + b0.y);
    __half2 h1 = __floats2half2_rn(d0z*inv*g0.z + b0.z, d0w*inv*g0.w + b0.w);
    __half2 h2 = __floats2half2_rn(d1x*inv*g1v.x + b1v.x, d1y*inv*g1v.y + b1v.y);
    __half2 h3 = __floats2half2_rn(d1z*inv*g1v.z + b1v.z, d1w*inv*g1v.w + b1v.w);

    __half* outp = &g_xnh[(size_t)r*CCH];
    ((uint2*)outp)[lane]      = make_uint2(*(uint32_t*)&h0, *(uint32_t*)&h1);
    ((uint2*)outp)[lane + 32] = make_uint2(*(uint32_t*)&h2, *(uint32_t*)&h3);
}

// ---------------- Windowed attention: mma.sync, 49-row smem, 4 blocks/SM -----
// 4 warps/block; each warp = one (window, head). grid = BWIN*2.
#define AQ_S  40                      // q/k smem row stride (halves); 80B = 16B-mult
#define AV_S  72                      // vt row stride; 144B = 16B-mult
#define AH_REG ((49*AQ_S + 49*AQ_S + 32*AV_S)*2)   // 12448 B per head
#define ATTN_SM (4*AH_REG + 4*169*4)               // 52496 B -> 4 blocks/SM

__global__ __launch_bounds__(128) void attn_kernel() {
    extern __shared__ char asmem[];
    int tid = threadIdx.x, lane = tid & 31, w = tid >> 5;
    int win  = blockIdx.x >> 1;
    int head = (blockIdx.x & 1)*4 + w;

    __half* qs = (__half*)(asmem + (size_t)w*AH_REG);
    __half* ks = qs + 49*AQ_S;
    __half* vt = ks + 49*AQ_S;
    float*  pos_s = (float*)(asmem + 4*AH_REG) + w*169;

    size_t base = ((size_t)win*NHH + head)*(NWT*HD);
    const __half2* qp = (const __half2*)&g_q[base];
    const __half2* kp = (const __half2*)&g_k[base];
    const __half2* vp = (const __half2*)&g_v[base];

    for (int i = lane; i < NWT*16; i += 32) {
        int r = i >> 4, c2 = (i & 15)*2;
        *(__half2*)&qs[r*AQ_S + c2] = qp[i];
        *(__half2*)&ks[r*AQ_S + c2] = kp[i];
        __half2 v = vp[i];
        vt[(size_t)c2*AV_S + r]     = __low2half(v);
        vt[(size_t)(c2+1)*AV_S + r] = __high2half(v);
    }
    // zero vt k-columns 49..63 (probs there are exactly 0, but must avoid NaN)
    for (int i = lane; i < 32*16; i += 32) {
        int d = i >> 4, kk = 48 + (i & 15);
        if (kk >= NWT) vt[d*AV_S + kk] = __ushort_as_half(0);
    }
    for (int i = lane; i < 169; i += 32) pos_s[i] = g_pos[i*NHH + head];
    __syncwarp();

    uint32_t qb = smem_u32(qs), kb = smem_u32(ks), vb = smem_u32(vt);
    // clamped B-row for K: rows >=49 read row 48 (cols masked to -1e30 later)
    int krow = (lane & 7) + ((lane & 16) >> 1);
    const uint32_t voff = (uint32_t)(((lane & 7) + ((lane & 16) >> 1))*AV_S + (lane & 8)) * 2;

    #pragma unroll 1
    for (int mt = 0; mt < 4; mt++) {
        int m0 = mt*16;
        // clamped A rows: invalid rows (>=49) read row 48; outputs never stored
        int qrow = m0 + (lane & 15); if (qrow > 48) qrow = 48;
        uint32_t aoffc = (uint32_t)(qrow*AQ_S + ((lane & 16) >> 1)) * 2;
        uint32_t qa[2][4];
        ldsm4(qa[0], qb + aoffc);
        ldsm4(qa[1], qb + aoffc + 32);

        float sc[7][4];
        #pragma unroll
        for (int t = 0; t < 7; t++)
            #pragma unroll
            for (int e = 0; e < 4; e++) sc[t][e] = 0.f;

        #pragma unroll
        for (int kt2 = 0; kt2 < 2; kt2++)
            #pragma unroll
            for (int jn = 0; jn < 4; jn++) {
                int kr = jn*16 + krow; if (kr > 48) kr = 48;
                uint32_t r[4];
                ldsm4(r, kb + (uint32_t)(kr*AQ_S + (lane & 8) + kt2*16)*2);
                mma16816(sc[jn*2], qa[kt2], r);
                if (jn*2 + 1 < 7) mma16816(sc[jn*2+1], qa[kt2], r+2);
            }

        int ra = m0 + (lane >> 2), rb2 = ra + 8;
        bool va = ra < NWT, vbv = rb2 < NWT;
        int raq = ra/GW, rar = ra - raq*GW;
        int rbq = rb2/GW, rbr = rb2 - rbq*GW;
        float mxa = -1e30f, mxb = -1e30f;
        #pragma unroll
        for (int t = 0; t < 7; t++) {
            #pragma unroll
            for (int e = 0; e < 2; e++) {
                int c = t*8 + (lane & 3)*2 + e;
                if (c < NWT) {
                    int cq = c/GW, cr = c - cq*GW;
                    if (va)  sc[t][e]   += pos_s[(raq-cq+6)*13 + (rar-cr+6)];
                    if (vbv) sc[t][2+e] += pos_s[(rbq-cq+6)*13 + (rbr-cr+6)];
                } else {
                    sc[t][e] = -1e30f; sc[t][2+e] = -1e30f;
                }
            }
            mxa = fmaxf(mxa, fmaxf(sc[t][0], sc[t][1]));
            mxb = fmaxf(mxb, fmaxf(sc[t][2], sc[t][3]));
        }
        mxa = fmaxf(mxa, __shfl_xor_sync(0xffffffffu, mxa, 1));
        mxa = fmaxf(mxa, __shfl_xor_sync(0xffffffffu, mxa, 2));
        mxb = fmaxf(mxb, __shfl_xor_sync(0xffffffffu, mxb, 1));
        mxb = fmaxf(mxb, __shfl_xor_sync(0xffffffffu, mxb, 2));

        float sa = 0.f, sb = 0.f;
        #pragma unroll
        for (int t = 0; t < 7; t++) {
            sc[t][0] = __expf(sc[t][0] - mxa);
            sc[t][1] = __expf(sc[t][1] - mxa);
            sc[t][2] = __expf(sc[t][2] - mxb);
            sc[t][3] = __expf(sc[t][3] - mxb);
            sa += sc[t][0] + sc[t][1];
            sb += sc[t][2] + sc[t][3];
        }
        sa += __shfl_xor_sync(0xffffffffu, sa, 1);
        sa += __shfl_xor_sync(0xffffffffu, sa, 2);
        sb += __shfl_xor_sync(0xffffffffu, sb, 1);
        sb += __shfl_xor_sync(0xffffffffu, sb, 2);
        float ia = 1.f/sa, ib = 1.f/sb;

        // pack probs directly into PV A-fragments (C layout == A layout)
        uint32_t pa[4][4];
        #pragma unroll
        for (int kt = 0; kt < 4; kt++) {
            int t0 = 2*kt, t1 = 2*kt + 1;
            __half2 h;
            h = __floats2half2_rn(sc[t0][0]*ia, sc[t0][1]*ia); pa[kt][0] = *(uint32_t*)&h;
            h = __floats2half2_rn(sc[t0][2]*ib, sc[t0][3]*ib); pa[kt][1] = *(uint32_t*)&h;
            if (t1 < 7) {
                h = __floats2half2_rn(sc[t1][0]*ia, sc[t1][1]*ia); pa[kt][2] = *(uint32_t*)&h;
                h = __floats2half2_rn(sc[t1][2]*ib, sc[t1][3]*ib); pa[kt][3] = *(uint32_t*)&h;
            } else { pa[kt][2] = 0; pa[kt][3] = 0; }
        }

        float ov[4][4];
        #pragma unroll
        for (int dt = 0; dt < 4; dt++)
            #pragma unroll
            for (int e = 0; e < 4; e++) ov[dt][e] = 0.f;
        #pragma unroll
        for (int kt = 0; kt < 4; kt++) {
            uint32_t v0[4], v1[4];
            ldsm4(v0, vb + voff + (uint32_t)(kt*16)*2);
            ldsm4(v1, vb + voff + (uint32_t)(16*AV_S + kt*16)*2);
            mma16816(ov[0], pa[kt], v0);
            mma16816(ov[1], pa[kt], v0+2);
            mma16816(ov[2], pa[kt], v1);
            mma16816(ov[3], pa[kt], v1+2);
        }

        #pragma unroll
        for (int dt = 0; dt < 4; dt++) {
            int c = dt*8 + (lane & 3)*2;
            if (va) {
                size_t o = ((size_t)win*NWT + ra)*CCH + head*HD + c;
                *(__half2*)&g_awinh[o] = __floats2half2_rn(ov[dt][0], ov[dt][1]);
            }
            if (vbv) {
                size_t o = ((size_t)win*NWT + rb2)*CCH + head*HD + c;
                *(__half2*)&g_awinh[o] = __floats2half2_rn(ov[dt][2], ov[dt][3]);
            }
        }
    }
}

// ---------------- launch ----------------------------------------------------
extern "C" void kernel_launch(void* const* d_in, const int* in_sizes, int n_in,
                              void* d_out, int out_size) {
    const float* x        = (const float*)d_in[0];
    const float* norm1_g  = (const float*)d_in[1];
    const float* norm1_b  = (const float*)d_in[2];
    const float* qkv_w    = (const float*)d_in[3];
    const float* qkv_b    = (const float*)d_in[4];
    const float* proj_w   = (const float*)d_in[5];
    const float* proj_b   = (const float*)d_in[6];
    const float* pos_pw   = (const float*)d_in[7];
    const float* pos_pb   = (const float*)d_in[8];
    const float* p1g      = (const float*)d_in[9];
    const float* p1b      = (const float*)d_in[10];
    const float* p1w      = (const float*)d_in[11];
    const float* p1wb     = (const float*)d_in[12];
    const float* p2g      = (const float*)d_in[13];
    const float* p2b      = (const float*)d_in[14];
    const float* p2w      = (const float*)d_in[15];
    const float* p2wb     = (const float*)d_in[16];
    const float* p3g      = (const float*)d_in[17];
    const float* p3b      = (const float*)d_in[18];
    const float* p3w      = (const float*)d_in[19];
    const float* p3wb     = (const float*)d_in[20];
    const float* norm2_g  = (const float*)d_in[21];
    const float* norm2_b  = (const float*)d_in[22];
    const float* fc1_w    = (const float*)d_in[23];
    const float* fc1_b    = (const float*)d_in[24];
    const float* fc2_w    = (const float*)d_in[25];
    const float* fc2_b    = (const float*)d_in[26];
    float* out = (float*)d_out;

    cudaFuncSetAttribute(gemm_mma<0,768,256>,  cudaFuncAttributeMaxDynamicSharedMemorySize, SMEM_TOT);
    cudaFuncSetAttribute(gemm_mma<1,256,256>,  cudaFuncAttributeMaxDynamicSharedMemorySize, SMEM_TOT);
    cudaFuncSetAttribute(gemm_mma<2,1024,256>, cudaFuncAttributeMaxDynamicSharedMemorySize, SMEM_TOT);
    cudaFuncSetAttribute(gemm_mma<3,256,1024>, cudaFuncAttributeMaxDynamicSharedMemorySize, SMEM_TOT);
    cudaFuncSetAttribute(attn_kernel, cudaFuncAttributeMaxDynamicSharedMemorySize, ATTN_SM);

    // launch order: prep(0), ln1(1), qkv(2), attn(3) -> ncu profiles attn
    prep_kernel<<<3073, 256>>>(qkv_w, proj_w, fc1_w, fc2_w,
                               pos_pw, pos_pb, p1g, p1b, p1w, p1wb,
                               p2g, p2b, p2w, p2wb, p3g, p3b, p3w, p3wb);
    ln_kernel<<<ROWS/8, 256>>>(x, norm1_g, norm1_b, 0);
    gemm_mma<0,768,256><<<dim3(6, ROWS/128), 256, SMEM_TOT>>>(WOFF_QKV, qkv_b, nullptr, nullptr);
    attn_kernel<<<BWIN*2, 128, ATTN_SM>>>();
    gemm_mma<1,256,256><<<dim3(2, ROWS/128), 256, SMEM_TOT>>>(WOFF_PROJ, proj_b, x, nullptr);
    ln_kernel<<<ROWS/8, 256>>>(nullptr, norm2_g, norm2_b, 1);
    gemm_mma<2,1024,256><<<dim3(8, ROWS/128), 256, SMEM_TOT>>>(WOFF_FC1, fc1_b, nullptr, nullptr);
    gemm_mma<3,256,1024><<<dim3(2, ROWS/128), 256, SMEM_TOT>>>(WOFF_FC2, fc2_b, nullptr, out);
}